// round 7
// baseline (speedup 1.0000x reference)
#include <cuda_runtime.h>
#include <cstdint>

#define N_NODES 100000
#define E_EDGES 3200000
#define D_IN   512
#define D_H    128
#define D_O    64
#define NEG_SLOPE 0.01f

// ---------------- scratch (device globals; no allocation allowed) ----------------
__device__ float g_h1 [N_NODES * D_H];   // 51.2 MB
__device__ float g_h2 [N_NODES * D_O];   // 25.6 MB
__device__ float g_u  [N_NODES * D_O];   // 25.6 MB  (t * dinv, pre-scaled messages)
__device__ float g_acc[N_NODES * D_O];   // 25.6 MB
__device__ float g_h3 [N_NODES * D_O];   // 25.6 MB
__device__ float g_deg [N_NODES];
__device__ float g_dinv[N_NODES];

__device__ __forceinline__ float lrelu(float v) {
    return v >= 0.0f ? v : NEG_SLOPE * v;
}

__device__ __forceinline__ uint32_t f2tf32(float f) {
    uint32_t u;
    asm("cvt.rna.tf32.f32 %0, %1;" : "=r"(u) : "f"(f));
    return u;
}

// =====================================================================
// gemm1: tf32 tensor-core GEMM  C[M,128] = lrelu(A[M,512] @ B[512,128] + bias)
// BM=128 BN=128 BK=32, 256 threads = 8 warps (4 along M x 2 along N),
// warp tile 32x64 = 2x8 m16n8k8 fragments.
// Shared memory holds tiles in FRAGMENT-MAJOR layout so the mainloop reads
// A fragments with one LDS.128 and B fragments with one LDS.64 per tile.
// =====================================================================
__global__ __launch_bounds__(256) void gemm1_tf32_kernel(
    const float* __restrict__ A,
    const float* __restrict__ B,
    const float* __restrict__ bias,
    float* __restrict__ C,
    int M)
{
    // smA: [mi(8)][ki(4)][lane(32)][4]   smB: [ni(16)][ki(4)][lane(32)][2]
    __shared__ uint32_t smA[8 * 4 * 32 * 4];   // 16 KB
    __shared__ uint32_t smB[16 * 4 * 32 * 2];  // 16 KB

    const int tid  = threadIdx.x;
    const int lane = tid & 31;
    const int warp = tid >> 5;
    const int warpM = warp & 3;       // 0..3
    const int warpN = warp >> 2;      // 0..1
    const int row0 = blockIdx.x * 128;
    const int miBase = warpM * 2;
    const int niBase = warpN * 8;

    float acc[2][8][4];
#pragma unroll
    for (int m = 0; m < 2; m++)
#pragma unroll
        for (int n = 0; n < 8; n++)
#pragma unroll
            for (int v = 0; v < 4; v++) acc[m][n][v] = 0.0f;

    float4 pa[4], pb[4];

    // ---- gmem tile load into regs (k0 = tile base in K) ----
    auto g_load = [&](int k0) {
#pragma unroll
        for (int i = 0; i < 4; i++) {
            int li = tid + i * 256;          // 0..1023
            int r  = li >> 3;                // 0..127
            int kc = li & 7;                 // float4 chunk in BK
            int gr = row0 + r;
            if (gr < M)
                pa[i] = *(const float4*)&A[(long long)gr * D_IN + k0 + kc * 4];
            else
                pa[i] = make_float4(0.f, 0.f, 0.f, 0.f);
        }
#pragma unroll
        for (int i = 0; i < 4; i++) {
            int li   = tid + i * 256;
            int krow = li >> 5;              // 0..31
            int nc   = li & 31;              // float4 chunk in BN
            pb[i] = *(const float4*)&B[(long long)(k0 + krow) * D_H + nc * 4];
        }
    };

    // ---- regs -> fragment-major smem (with fp32->tf32 convert) ----
    auto s_store = [&]() {
#pragma unroll
        for (int i = 0; i < 4; i++) {
            int li = tid + i * 256;
            int r  = li >> 3;
            int kc = li & 7;
            int ki = kc >> 1;                         // k-step (8 wide)
            int p  = ((r & 15) >= 8 ? 1 : 0) + ((kc & 1) ? 2 : 0);
            int mi = r >> 4;
            int laneBase = (r & 7) * 4;
            uint32_t* s = &smA[((mi * 4 + ki) * 32 + laneBase) * 4 + p];
            s[0 * 4] = f2tf32(pa[i].x);
            s[1 * 4] = f2tf32(pa[i].y);
            s[2 * 4] = f2tf32(pa[i].z);
            s[3 * 4] = f2tf32(pa[i].w);
        }
#pragma unroll
        for (int i = 0; i < 4; i++) {
            int li   = tid + i * 256;
            int krow = li >> 5;
            int nc   = li & 31;
            int ki   = krow >> 3;
            int kr   = krow & 7;
            int t    = kr & 3;
            int vidx = (kr >> 2) & 1;
            int n    = nc * 4;
            int ni   = n >> 3;
            int c8b  = n & 7;                         // 0 or 4
            uint32_t* s = &smB[((ni * 4 + ki) * 32 + (c8b * 4 + t)) * 2 + vidx];
            s[0 * 8] = f2tf32(pb[i].x);               // lane step 4 -> 8 uints
            s[1 * 8] = f2tf32(pb[i].y);
            s[2 * 8] = f2tf32(pb[i].z);
            s[3 * 8] = f2tf32(pb[i].w);
        }
    };

    auto compute = [&]() {
#pragma unroll
        for (int ki = 0; ki < 4; ki++) {
            uint4 af[2];
            uint2 bf[8];
#pragma unroll
            for (int m = 0; m < 2; m++)
                af[m] = *(uint4*)&smA[(((miBase + m) * 4 + ki) * 32 + lane) * 4];
#pragma unroll
            for (int n = 0; n < 8; n++)
                bf[n] = *(uint2*)&smB[(((niBase + n) * 4 + ki) * 32 + lane) * 2];
#pragma unroll
            for (int m = 0; m < 2; m++)
#pragma unroll
                for (int n = 0; n < 8; n++) {
                    asm volatile(
                        "mma.sync.aligned.m16n8k8.row.col.f32.tf32.tf32.f32 "
                        "{%0,%1,%2,%3}, {%4,%5,%6,%7}, {%8,%9}, {%0,%1,%2,%3};"
                        : "+f"(acc[m][n][0]), "+f"(acc[m][n][1]),
                          "+f"(acc[m][n][2]), "+f"(acc[m][n][3])
                        : "r"(af[m].x), "r"(af[m].y), "r"(af[m].z), "r"(af[m].w),
                          "r"(bf[n].x), "r"(bf[n].y));
                }
        }
    };

    // ---- mainloop: 512 / 32 = 16 K-tiles, register prefetch ----
    g_load(0);
    s_store();
    __syncthreads();
#pragma unroll 1
    for (int kt = 0; kt < 16; kt++) {
        if (kt + 1 < 16) g_load((kt + 1) * 32);
        compute();
        __syncthreads();
        if (kt + 1 < 16) {
            s_store();
            __syncthreads();
        }
    }

    // ---- epilogue: bias + leaky relu ----
#pragma unroll
    for (int m = 0; m < 2; m++) {
        int rHi = row0 + warpM * 32 + m * 16 + (lane >> 2);
        int rLo = rHi + 8;
#pragma unroll
        for (int n = 0; n < 8; n++) {
            int col = warpN * 64 + n * 8 + (lane & 3) * 2;
            float b0 = bias[col], b1 = bias[col + 1];
            if (rHi < M) {
                float2 v;
                v.x = lrelu(acc[m][n][0] + b0);
                v.y = lrelu(acc[m][n][1] + b1);
                *(float2*)&C[(long long)rHi * D_H + col] = v;
            }
            if (rLo < M) {
                float2 v;
                v.x = lrelu(acc[m][n][2] + b0);
                v.y = lrelu(acc[m][n][3] + b1);
                *(float2*)&C[(long long)rLo * D_H + col] = v;
            }
        }
    }
}

// ---------------- fp32 SGEMM, 8x8 register tiles, single column-block (N == BN) ----------------
// SCALE_DINV: multiply each output row by g_dinv[row] in the epilogue (u = t * dinv)
template<int BM, int BN, int BK, bool RELU, bool ADD_BIAS, bool SCALE_DINV>
__global__ void gemm_kernel(const float* __restrict__ A,
                            const float* __restrict__ B,
                            const float* __restrict__ bias,
                            float* __restrict__ C,
                            int M, int K) {
    constexpr int TM = 8, TN = 8;
    constexpr int TX = BN / TN;
    constexpr int TY = BM / TM;
    constexpr int THREADS = TX * TY;
    constexpr int KC = BK / 4;              // float4 chunks per A row slice
    constexpr int L4A = BM * BK / (4 * THREADS);
    constexpr int L4B = BK * BN / (4 * THREADS);

    __shared__ float As[BK][BM];
    __shared__ float Bs[BK][BN];

    const int tid  = threadIdx.x;
    const int tx   = tid % TX;
    const int ty   = tid / TX;
    const int row0 = blockIdx.x * BM;

    float acc[TM][TN];
#pragma unroll
    for (int i = 0; i < TM; i++)
#pragma unroll
        for (int j = 0; j < TN; j++) acc[i][j] = 0.0f;

    for (int k0 = 0; k0 < K; k0 += BK) {
        // load A tile (BM x BK), stored transposed As[k][m]
#pragma unroll
        for (int l = 0; l < L4A; l++) {
            int li = tid + l * THREADS;
            int r  = li / KC;
            int kc = li % KC;
            float4 f = make_float4(0.f, 0.f, 0.f, 0.f);
            int gr = row0 + r;
            if (gr < M)
                f = *(const float4*)&A[(long long)gr * K + k0 + kc * 4];
            As[kc * 4 + 0][r] = f.x;
            As[kc * 4 + 1][r] = f.y;
            As[kc * 4 + 2][r] = f.z;
            As[kc * 4 + 3][r] = f.w;
        }
        // load B tile (BK x BN)
#pragma unroll
        for (int l = 0; l < L4B; l++) {
            int li = tid + l * THREADS;
            int r  = li / (BN / 4);
            int c  = li % (BN / 4);
            *(float4*)&Bs[r][c * 4] =
                *(const float4*)&B[(long long)(k0 + r) * BN + c * 4];
        }
        __syncthreads();

#pragma unroll
        for (int kk = 0; kk < BK; kk++) {
            float ra[TM], rb[TN];
#pragma unroll
            for (int i = 0; i < TM; i += 4)
                *(float4*)&ra[i] = *(float4*)&As[kk][ty * TM + i];
#pragma unroll
            for (int j = 0; j < TN; j += 4)
                *(float4*)&rb[j] = *(float4*)&Bs[kk][tx * TN + j];
#pragma unroll
            for (int i = 0; i < TM; i++)
#pragma unroll
                for (int j = 0; j < TN; j++)
                    acc[i][j] += ra[i] * rb[j];
        }
        __syncthreads();
    }

#pragma unroll
    for (int i = 0; i < TM; i++) {
        int gr = row0 + ty * TM + i;
        if (gr >= M) continue;
        float sc = 1.0f;
        if (SCALE_DINV) sc = g_dinv[gr];
#pragma unroll
        for (int j = 0; j < TN; j += 4) {
            float4 v = *(float4*)&acc[i][j];
            int gc = tx * TN + j;
            if (ADD_BIAS) {
                v.x += bias[gc + 0]; v.y += bias[gc + 1];
                v.z += bias[gc + 2]; v.w += bias[gc + 3];
            }
            if (SCALE_DINV) {
                v.x *= sc; v.y *= sc; v.z *= sc; v.w *= sc;
            }
            if (RELU) {
                v.x = lrelu(v.x); v.y = lrelu(v.y);
                v.z = lrelu(v.z); v.w = lrelu(v.w);
            }
            *(float4*)&C[(long long)gr * BN + gc] = v;
        }
    }
}

// ---------------- degree / normalization ----------------
__global__ void init_deg_kernel() {
    int i = blockIdx.x * blockDim.x + threadIdx.x;
    if (i < N_NODES) g_deg[i] = 1.0f;           // self-loop
}

__global__ void count_deg_kernel(const int* __restrict__ dst) {
    int e = blockIdx.x * blockDim.x + threadIdx.x;
    if (e < E_EDGES) atomicAdd(&g_deg[dst[e]], 1.0f);
}

__global__ void calc_dinv_kernel() {
    int i = blockIdx.x * blockDim.x + threadIdx.x;
    if (i < N_NODES) g_dinv[i] = rsqrtf(g_deg[i]);   // deg >= 1 always
}

// ---------------- edge scatter: acc[d] += u[s]  (u already scaled by dinv[s]) ----------------
// one thread per (edge, float4 chunk): 16 chunks of 4 floats per edge
__global__ void edge_scatter_kernel(const int* __restrict__ src,
                                    const int* __restrict__ dst,
                                    const float* __restrict__ u) {
    long long idx = (long long)blockIdx.x * blockDim.x + threadIdx.x;
    if (idx >= (long long)E_EDGES * 16) return;
    int e = (int)(idx >> 4);
    int c = ((int)idx & 15) << 2;
    int s = __ldg(&src[e]);
    int d = __ldg(&dst[e]);
    float4 v = *(const float4*)&u[(long long)s * D_O + c];
    float* p = &g_acc[(long long)d * D_O + c];
    asm volatile("red.global.add.v4.f32 [%0], {%1,%2,%3,%4};"
                 :: "l"(p), "f"(v.x), "f"(v.y), "f"(v.z), "f"(v.w)
                 : "memory");
}

// ---------------- finalize: out = lrelu(dinv[n]*(acc[n] + u[n]) + b) ----------------
// (u[n]*dinv[n] is exactly the self-loop term t[n]*dinv[n]^2)
__global__ void finalize_kernel(const float* __restrict__ u,
                                const float* __restrict__ bias,
                                float* __restrict__ out) {
    int idx = blockIdx.x * blockDim.x + threadIdx.x;
    if (idx >= N_NODES * 16) return;
    int n = idx >> 4;
    int c = (idx & 15) << 2;
    float di = g_dinv[n];
    float4 a  = *(float4*)&g_acc[(long long)n * D_O + c];
    float4 uv = *(const float4*)&u[(long long)n * D_O + c];
    float4 b  = *(const float4*)&bias[c];
    a.x = lrelu(di * (a.x + uv.x) + b.x);
    a.y = lrelu(di * (a.y + uv.y) + b.y);
    a.z = lrelu(di * (a.z + uv.z) + b.z);
    a.w = lrelu(di * (a.w + uv.w) + b.w);
    *(float4*)&out[(long long)n * D_O + c] = a;
}

// ---------------- classifier: logits = h @ Wc + bc ----------------
__global__ void classifier_kernel(const float* __restrict__ h,
                                  const float* __restrict__ Wc,
                                  const float* __restrict__ bc,
                                  float* __restrict__ out) {
    __shared__ float w[D_O * 2];
    __shared__ float b2s[2];
    if (threadIdx.x < D_O * 2) w[threadIdx.x] = Wc[threadIdx.x];
    if (threadIdx.x < 2) b2s[threadIdx.x] = bc[threadIdx.x];
    __syncthreads();
    int n = blockIdx.x * blockDim.x + threadIdx.x;
    if (n >= N_NODES) return;
    float a0 = b2s[0], a1 = b2s[1];
    const float* hr = h + (long long)n * D_O;
#pragma unroll
    for (int k = 0; k < D_O; k++) {
        float v = hr[k];
        a0 += v * w[k * 2 + 0];
        a1 += v * w[k * 2 + 1];
    }
    out[n * 2 + 0] = a0;
    out[n * 2 + 1] = a1;
}

// ---------------- host launcher ----------------
extern "C" void kernel_launch(void* const* d_in, const int* in_sizes, int n_in,
                              void* d_out, int out_size) {
    const float* x   = (const float*)d_in[0];
    const int*   ei  = (const int*)  d_in[1];
    const float* W1  = (const float*)d_in[2];
    const float* b1  = (const float*)d_in[3];
    const float* W2  = (const float*)d_in[4];
    const float* b2  = (const float*)d_in[5];
    const float* Wg1 = (const float*)d_in[6];
    const float* bg1 = (const float*)d_in[7];
    const float* Wg2 = (const float*)d_in[8];
    const float* bg2 = (const float*)d_in[9];
    const float* Wc  = (const float*)d_in[10];
    const float* bc  = (const float*)d_in[11];
    float* out = (float*)d_out;

    const int* src = ei;
    const int* dst = ei + E_EDGES;

    float *h1, *h2, *u, *h3, *acc;
    cudaGetSymbolAddress((void**)&h1,  g_h1);
    cudaGetSymbolAddress((void**)&h2,  g_h2);
    cudaGetSymbolAddress((void**)&u,   g_u);
    cudaGetSymbolAddress((void**)&h3,  g_h3);
    cudaGetSymbolAddress((void**)&acc, g_acc);

    float* logits = out;                      // [N, 2]
    float* h4     = out + 2 * N_NODES;        // [N, 64]  (final h, also classifier input)

    const int MBLK = (N_NODES + 127) / 128;   // 782

    // degrees / symmetric norm first (gemm epilogues consume g_dinv)
    init_deg_kernel <<<(N_NODES + 255) / 256, 256>>>();
    count_deg_kernel<<<(E_EDGES + 255) / 256, 256>>>(dst);
    calc_dinv_kernel<<<(N_NODES + 255) / 256, 256>>>();

    // encoder
    gemm1_tf32_kernel<<<MBLK, 256>>>(x, W1, b1, h1, N_NODES);
    gemm_kernel<128,  64, 16, true, true, false><<<MBLK, 128>>>(h1, W2, b2, h2, N_NODES, D_H);

    const long long SCAT_THREADS = (long long)E_EDGES * 16;
    const int SCAT_BLOCKS = (int)((SCAT_THREADS + 255) / 256);
    const int FIN_BLOCKS  = (N_NODES * 16 + 255) / 256;
    const size_t ACC_BYTES = (size_t)N_NODES * D_O * sizeof(float);

    // GCN layer 1: h3 = lrelu(dinv*(acc + u) + bg1), u = (h2 @ Wg1) * dinv
    gemm_kernel<128, 64, 16, false, false, true><<<MBLK, 128>>>(h2, Wg1, nullptr, u, N_NODES, D_O);
    cudaMemsetAsync(acc, 0, ACC_BYTES);
    edge_scatter_kernel<<<SCAT_BLOCKS, 256>>>(src, dst, u);
    finalize_kernel<<<FIN_BLOCKS, 256>>>(u, bg1, h3);

    // GCN layer 2 -> h4 straight into d_out
    gemm_kernel<128, 64, 16, false, false, true><<<MBLK, 128>>>(h3, Wg2, nullptr, u, N_NODES, D_O);
    cudaMemsetAsync(acc, 0, ACC_BYTES);
    edge_scatter_kernel<<<SCAT_BLOCKS, 256>>>(src, dst, u);
    finalize_kernel<<<FIN_BLOCKS, 256>>>(u, bg2, h4);

    // classifier
    classifier_kernel<<<(N_NODES + 255) / 256, 256>>>(h4, Wc, bc, logits);
}

// round 11
// speedup vs baseline: 1.3799x; 1.3799x over previous
#include <cuda_runtime.h>
#include <cuda_bf16.h>
#include <cstdint>

#define N_NODES 100000
#define E_EDGES 3200000
#define D_IN   512
#define D_H    128
#define D_O    64
#define NEG_SLOPE 0.01f

// ---------------- scratch (device globals; no allocation allowed) ----------------
__device__ float g_h1 [N_NODES * D_H];   // 51.2 MB
__device__ float g_h2 [N_NODES * D_O];   // 25.6 MB
__device__ float g_u  [N_NODES * D_O];   // 25.6 MB  (t * dinv, pre-scaled messages)
__device__ float g_acc[N_NODES * D_O];   // 25.6 MB
__device__ float g_h3 [N_NODES * D_O];   // 25.6 MB
__device__ float g_deg [N_NODES];
__device__ float g_dinv[N_NODES];
__device__ __nv_bfloat16 g_w1t[D_H * D_IN];  // W1 transposed -> [128][512] bf16, K-major

__device__ __forceinline__ float lrelu(float v) {
    return v >= 0.0f ? v : NEG_SLOPE * v;
}

__device__ __forceinline__ uint32_t smem_u32(const void* p) {
    uint32_t a;
    asm("{ .reg .u64 t; cvta.to.shared.u64 t, %1; cvt.u32.u64 %0, t; }" : "=r"(a) : "l"(p));
    return a;
}
__device__ __forceinline__ uint32_t pack_bf16x2(float lo, float hi) {
    uint32_t r;
    asm("cvt.rn.satfinite.bf16x2.f32 %0, %1, %2;" : "=r"(r) : "f"(hi), "f"(lo));
    return r;
}
__device__ __forceinline__ void ldsm4(uint32_t& r0, uint32_t& r1, uint32_t& r2, uint32_t& r3,
                                      uint32_t addr) {
    asm volatile("ldmatrix.sync.aligned.m8n8.x4.shared.b16 {%0,%1,%2,%3}, [%4];"
                 : "=r"(r0), "=r"(r1), "=r"(r2), "=r"(r3) : "r"(addr));
}
__device__ __forceinline__ void mma_bf16(float* d, const uint32_t* a, const uint32_t* b) {
    asm volatile(
        "mma.sync.aligned.m16n8k16.row.col.f32.bf16.bf16.f32 "
        "{%0,%1,%2,%3}, {%4,%5,%6,%7}, {%8,%9}, {%0,%1,%2,%3};"
        : "+f"(d[0]), "+f"(d[1]), "+f"(d[2]), "+f"(d[3])
        : "r"(a[0]), "r"(a[1]), "r"(a[2]), "r"(a[3]), "r"(b[0]), "r"(b[1]));
}
// SW128 swizzle: XOR byte bits [6:4] with row bits [2:0] (128B rows)
#define SW128(o) ((o) ^ ((((uint32_t)(o)) >> 3) & 0x70))

// =====================================================================
// gemm1: bf16 HMMA GEMM  C[M,128] = lrelu(A[M,512] @ W1 + bias)
// BM=128 BN=128 BK=64, 256 threads = 8 warps (4 M x 2 N), warp tile 32x64.
// A tile f32->bf16 into SW128 smem (128B rows), B from pre-transposed bf16
// W1t[128][512]. Fragments via ldmatrix.x4, 16 m16n8k16 MMAs per k-step.
// =====================================================================
__global__ __launch_bounds__(256) void gemm1_bf16_kernel(
    const float* __restrict__ A,
    const float* __restrict__ bias,
    float* __restrict__ C,
    int M)
{
    __shared__ __align__(1024) char smA[16384];   // 128 x 64 bf16, SW128
    __shared__ __align__(1024) char smB[16384];   // 128(n) x 64(k) bf16, SW128

    const int tid  = threadIdx.x;
    const int lane = tid & 31;
    const int warp = tid >> 5;
    const int warpM = warp & 3;
    const int warpN = warp >> 2;
    const int row0 = blockIdx.x * 128;

    const uint32_t baseA = smem_u32(smA);
    const uint32_t baseB = smem_u32(smB);
    const __nv_bfloat16* __restrict__ Bt = g_w1t;

    float acc[2][8][4];
#pragma unroll
    for (int m = 0; m < 2; m++)
#pragma unroll
        for (int n = 0; n < 8; n++)
#pragma unroll
            for (int v = 0; v < 4; v++) acc[m][n][v] = 0.0f;

    // ldmatrix per-lane row/col components
    const int matid = lane >> 3;          // 0..3
    const int matrow = lane & 7;
    // A frag (m16 x k16): rowAdd = (mat&1)*8, colAdd = (mat>>1)*16
    const int aRowOff = (matid & 1) * 8 + matrow;
    const int aColOff = (matid >> 1) * 16;
    // B frag pair (n16 x k16): rowAdd = (mat>>1)*8, colAdd = (mat&1)*16
    const int bRowOff = (matid >> 1) * 8 + matrow;
    const int bColOff = (matid & 1) * 16;

    float4 pa[8];
    uint4  pb[4];

    auto g_load = [&](int k0) {
#pragma unroll
        for (int i = 0; i < 8; i++) {
            int li = tid + i * 256;          // 0..2047
            int r  = li >> 4;                // row 0..127
            int q  = li & 15;                // float4 chunk 0..15 (64 f32)
            int gr = row0 + r;
            pa[i] = (gr < M) ? *(const float4*)&A[(size_t)gr * D_IN + k0 + q * 4]
                             : make_float4(0.f, 0.f, 0.f, 0.f);
        }
#pragma unroll
        for (int i = 0; i < 4; i++) {
            int li = tid + i * 256;          // 0..1023
            int n  = li >> 3;                // n row 0..127
            int q  = li & 7;                 // uint4 chunk (16B = 8 bf16)
            pb[i] = *(const uint4*)&Bt[(size_t)n * D_IN + k0 + q * 8];
        }
    };

    auto s_store = [&]() {
#pragma unroll
        for (int i = 0; i < 8; i++) {
            int li = tid + i * 256;
            int r  = li >> 4;
            int q  = li & 15;
            uint2 v;
            v.x = pack_bf16x2(pa[i].x, pa[i].y);
            v.y = pack_bf16x2(pa[i].z, pa[i].w);
            *(uint2*)&smA[SW128(r * 128 + q * 8)] = v;
        }
#pragma unroll
        for (int i = 0; i < 4; i++) {
            int li = tid + i * 256;
            int n  = li >> 3;
            int q  = li & 7;
            *(uint4*)&smB[SW128(n * 128 + q * 16)] = pb[i];
        }
    };

    auto compute = [&]() {
#pragma unroll
        for (int ks = 0; ks < 4; ks++) {
            const int kb = ks * 32;          // byte offset of k-step (16 bf16)
            uint32_t af[2][4];
            uint32_t bf[8][2];
#pragma unroll
            for (int m = 0; m < 2; m++) {
                int row = warpM * 32 + m * 16 + aRowOff;
                uint32_t addr = baseA + SW128(row * 128 + kb + aColOff);
                ldsm4(af[m][0], af[m][1], af[m][2], af[m][3], addr);
            }
#pragma unroll
            for (int p = 0; p < 4; p++) {
                int row = warpN * 64 + p * 16 + bRowOff;
                uint32_t addr = baseB + SW128(row * 128 + kb + bColOff);
                ldsm4(bf[2 * p][0], bf[2 * p][1], bf[2 * p + 1][0], bf[2 * p + 1][1], addr);
            }
#pragma unroll
            for (int m = 0; m < 2; m++)
#pragma unroll
                for (int n = 0; n < 8; n++)
                    mma_bf16(acc[m][n], af[m], bf[n]);
        }
    };

    // ---- mainloop: 512 / 64 = 8 K-tiles, register prefetch ----
    g_load(0);
    s_store();
    __syncthreads();
#pragma unroll 1
    for (int kt = 0; kt < 8; kt++) {
        if (kt + 1 < 8) g_load((kt + 1) * 64);
        compute();
        __syncthreads();
        if (kt + 1 < 8) {
            s_store();
            __syncthreads();
        }
    }

    // ---- epilogue: bias + leaky relu ----
#pragma unroll
    for (int m = 0; m < 2; m++) {
        int rHi = row0 + warpM * 32 + m * 16 + (lane >> 2);
        int rLo = rHi + 8;
#pragma unroll
        for (int n = 0; n < 8; n++) {
            int col = warpN * 64 + n * 8 + (lane & 3) * 2;
            float b0 = bias[col], b1 = bias[col + 1];
            if (rHi < M) {
                float2 v;
                v.x = lrelu(acc[m][n][0] + b0);
                v.y = lrelu(acc[m][n][1] + b1);
                *(float2*)&C[(size_t)rHi * D_H + col] = v;
            }
            if (rLo < M) {
                float2 v;
                v.x = lrelu(acc[m][n][2] + b0);
                v.y = lrelu(acc[m][n][3] + b1);
                *(float2*)&C[(size_t)rLo * D_H + col] = v;
            }
        }
    }
}

// ---------------- W1 [512,128] f32 -> W1t [128,512] bf16 (K-major) ----------------
__global__ void w1t_prep_kernel(const float* __restrict__ W1) {
    int idx = blockIdx.x * blockDim.x + threadIdx.x;   // n*512 + k
    if (idx >= D_H * D_IN) return;
    int n = idx >> 9;
    int k = idx & 511;
    g_w1t[idx] = __float2bfloat16(W1[k * D_H + n]);
}

// ---------------- fp32 SGEMM, 8x8 register tiles, single column-block (N == BN) ----------------
// SCALE_DINV: multiply each output row by g_dinv[row] in the epilogue (u = t * dinv)
template<int BM, int BN, int BK, bool RELU, bool ADD_BIAS, bool SCALE_DINV>
__global__ void gemm_kernel(const float* __restrict__ A,
                            const float* __restrict__ B,
                            const float* __restrict__ bias,
                            float* __restrict__ C,
                            int M, int K) {
    constexpr int TM = 8, TN = 8;
    constexpr int TX = BN / TN;
    constexpr int TY = BM / TM;
    constexpr int THREADS = TX * TY;
    constexpr int KC = BK / 4;              // float4 chunks per A row slice
    constexpr int L4A = BM * BK / (4 * THREADS);
    constexpr int L4B = BK * BN / (4 * THREADS);

    __shared__ float As[BK][BM];
    __shared__ float Bs[BK][BN];

    const int tid  = threadIdx.x;
    const int tx   = tid % TX;
    const int ty   = tid / TX;
    const int row0 = blockIdx.x * BM;

    float acc[TM][TN];
#pragma unroll
    for (int i = 0; i < TM; i++)
#pragma unroll
        for (int j = 0; j < TN; j++) acc[i][j] = 0.0f;

    for (int k0 = 0; k0 < K; k0 += BK) {
        // load A tile (BM x BK), stored transposed As[k][m]
#pragma unroll
        for (int l = 0; l < L4A; l++) {
            int li = tid + l * THREADS;
            int r  = li / KC;
            int kc = li % KC;
            float4 f = make_float4(0.f, 0.f, 0.f, 0.f);
            int gr = row0 + r;
            if (gr < M)
                f = *(const float4*)&A[(long long)gr * K + k0 + kc * 4];
            As[kc * 4 + 0][r] = f.x;
            As[kc * 4 + 1][r] = f.y;
            As[kc * 4 + 2][r] = f.z;
            As[kc * 4 + 3][r] = f.w;
        }
        // load B tile (BK x BN)
#pragma unroll
        for (int l = 0; l < L4B; l++) {
            int li = tid + l * THREADS;
            int r  = li / (BN / 4);
            int c  = li % (BN / 4);
            *(float4*)&Bs[r][c * 4] =
                *(const float4*)&B[(long long)(k0 + r) * BN + c * 4];
        }
        __syncthreads();

#pragma unroll
        for (int kk = 0; kk < BK; kk++) {
            float ra[TM], rb[TN];
#pragma unroll
            for (int i = 0; i < TM; i += 4)
                *(float4*)&ra[i] = *(float4*)&As[kk][ty * TM + i];
#pragma unroll
            for (int j = 0; j < TN; j += 4)
                *(float4*)&rb[j] = *(float4*)&Bs[kk][tx * TN + j];
#pragma unroll
            for (int i = 0; i < TM; i++)
#pragma unroll
                for (int j = 0; j < TN; j++)
                    acc[i][j] += ra[i] * rb[j];
        }
        __syncthreads();
    }

#pragma unroll
    for (int i = 0; i < TM; i++) {
        int gr = row0 + ty * TM + i;
        if (gr >= M) continue;
        float sc = 1.0f;
        if (SCALE_DINV) sc = g_dinv[gr];
#pragma unroll
        for (int j = 0; j < TN; j += 4) {
            float4 v = *(float4*)&acc[i][j];
            int gc = tx * TN + j;
            if (ADD_BIAS) {
                v.x += bias[gc + 0]; v.y += bias[gc + 1];
                v.z += bias[gc + 2]; v.w += bias[gc + 3];
            }
            if (SCALE_DINV) {
                v.x *= sc; v.y *= sc; v.z *= sc; v.w *= sc;
            }
            if (RELU) {
                v.x = lrelu(v.x); v.y = lrelu(v.y);
                v.z = lrelu(v.z); v.w = lrelu(v.w);
            }
            *(float4*)&C[(long long)gr * BN + gc] = v;
        }
    }
}

// ---------------- degree / normalization ----------------
__global__ void init_deg_kernel() {
    int i = blockIdx.x * blockDim.x + threadIdx.x;
    if (i < N_NODES) g_deg[i] = 1.0f;           // self-loop
}

__global__ void count_deg_kernel(const int* __restrict__ dst) {
    int e = blockIdx.x * blockDim.x + threadIdx.x;
    if (e < E_EDGES) atomicAdd(&g_deg[dst[e]], 1.0f);
}

__global__ void calc_dinv_kernel() {
    int i = blockIdx.x * blockDim.x + threadIdx.x;
    if (i < N_NODES) g_dinv[i] = rsqrtf(g_deg[i]);   // deg >= 1 always
}

// ---------------- edge scatter: acc[d] += u[s]  (u already scaled by dinv[s]) ----------------
// one thread per (edge, float4 chunk): 16 chunks of 4 floats per edge
__global__ void edge_scatter_kernel(const int* __restrict__ src,
                                    const int* __restrict__ dst,
                                    const float* __restrict__ u) {
    long long idx = (long long)blockIdx.x * blockDim.x + threadIdx.x;
    if (idx >= (long long)E_EDGES * 16) return;
    int e = (int)(idx >> 4);
    int c = ((int)idx & 15) << 2;
    int s = __ldg(&src[e]);
    int d = __ldg(&dst[e]);
    float4 v = *(const float4*)&u[(long long)s * D_O + c];
    float* p = &g_acc[(long long)d * D_O + c];
    asm volatile("red.global.add.v4.f32 [%0], {%1,%2,%3,%4};"
                 :: "l"(p), "f"(v.x), "f"(v.y), "f"(v.z), "f"(v.w)
                 : "memory");
}

// ---------------- finalize: out = lrelu(dinv[n]*(acc[n] + u[n]) + b) ----------------
// (u[n]*dinv[n] is exactly the self-loop term t[n]*dinv[n]^2)
__global__ void finalize_kernel(const float* __restrict__ u,
                                const float* __restrict__ bias,
                                float* __restrict__ out) {
    int idx = blockIdx.x * blockDim.x + threadIdx.x;
    if (idx >= N_NODES * 16) return;
    int n = idx >> 4;
    int c = (idx & 15) << 2;
    float di = g_dinv[n];
    float4 a  = *(float4*)&g_acc[(long long)n * D_O + c];
    float4 uv = *(const float4*)&u[(long long)n * D_O + c];
    float4 b  = *(const float4*)&bias[c];
    a.x = lrelu(di * (a.x + uv.x) + b.x);
    a.y = lrelu(di * (a.y + uv.y) + b.y);
    a.z = lrelu(di * (a.z + uv.z) + b.z);
    a.w = lrelu(di * (a.w + uv.w) + b.w);
    *(float4*)&out[(long long)n * D_O + c] = a;
}

// ---------------- classifier: logits = h @ Wc + bc ----------------
__global__ void classifier_kernel(const float* __restrict__ h,
                                  const float* __restrict__ Wc,
                                  const float* __restrict__ bc,
                                  float* __restrict__ out) {
    __shared__ float w[D_O * 2];
    __shared__ float b2s[2];
    if (threadIdx.x < D_O * 2) w[threadIdx.x] = Wc[threadIdx.x];
    if (threadIdx.x < 2) b2s[threadIdx.x] = bc[threadIdx.x];
    __syncthreads();
    int n = blockIdx.x * blockDim.x + threadIdx.x;
    if (n >= N_NODES) return;
    float a0 = b2s[0], a1 = b2s[1];
    const float* hr = h + (long long)n * D_O;
#pragma unroll
    for (int k = 0; k < D_O; k++) {
        float v = hr[k];
        a0 += v * w[k * 2 + 0];
        a1 += v * w[k * 2 + 1];
    }
    out[n * 2 + 0] = a0;
    out[n * 2 + 1] = a1;
}

// ---------------- host launcher ----------------
extern "C" void kernel_launch(void* const* d_in, const int* in_sizes, int n_in,
                              void* d_out, int out_size) {
    const float* x   = (const float*)d_in[0];
    const int*   ei  = (const int*)  d_in[1];
    const float* W1  = (const float*)d_in[2];
    const float* b1  = (const float*)d_in[3];
    const float* W2  = (const float*)d_in[4];
    const float* b2  = (const float*)d_in[5];
    const float* Wg1 = (const float*)d_in[6];
    const float* bg1 = (const float*)d_in[7];
    const float* Wg2 = (const float*)d_in[8];
    const float* bg2 = (const float*)d_in[9];
    const float* Wc  = (const float*)d_in[10];
    const float* bc  = (const float*)d_in[11];
    float* out = (float*)d_out;

    const int* src = ei;
    const int* dst = ei + E_EDGES;

    float *h1, *h2, *u, *h3, *acc;
    cudaGetSymbolAddress((void**)&h1,  g_h1);
    cudaGetSymbolAddress((void**)&h2,  g_h2);
    cudaGetSymbolAddress((void**)&u,   g_u);
    cudaGetSymbolAddress((void**)&h3,  g_h3);
    cudaGetSymbolAddress((void**)&acc, g_acc);

    float* logits = out;                      // [N, 2]
    float* h4     = out + 2 * N_NODES;        // [N, 64]  (final h, also classifier input)

    const int MBLK = (N_NODES + 127) / 128;   // 782

    // degrees / symmetric norm first (gemm epilogues consume g_dinv)
    init_deg_kernel <<<(N_NODES + 255) / 256, 256>>>();
    count_deg_kernel<<<(E_EDGES + 255) / 256, 256>>>(dst);
    calc_dinv_kernel<<<(N_NODES + 255) / 256, 256>>>();

    // encoder: gemm1 on bf16 HMMA, gemm2 fp32
    w1t_prep_kernel<<<(D_H * D_IN + 255) / 256, 256>>>(W1);
    gemm1_bf16_kernel<<<MBLK, 256>>>(x, b1, h1, N_NODES);
    gemm_kernel<128,  64, 16, true, true, false><<<MBLK, 128>>>(h1, W2, b2, h2, N_NODES, D_H);

    const long long SCAT_THREADS = (long long)E_EDGES * 16;
    const int SCAT_BLOCKS = (int)((SCAT_THREADS + 255) / 256);
    const int FIN_BLOCKS  = (N_NODES * 16 + 255) / 256;
    const size_t ACC_BYTES = (size_t)N_NODES * D_O * sizeof(float);

    // GCN layer 1: h3 = lrelu(dinv*(acc + u) + bg1), u = (h2 @ Wg1) * dinv
    gemm_kernel<128, 64, 16, false, false, true><<<MBLK, 128>>>(h2, Wg1, nullptr, u, N_NODES, D_O);
    cudaMemsetAsync(acc, 0, ACC_BYTES);
    edge_scatter_kernel<<<SCAT_BLOCKS, 256>>>(src, dst, u);
    finalize_kernel<<<FIN_BLOCKS, 256>>>(u, bg1, h3);

    // GCN layer 2 -> h4 straight into d_out
    gemm_kernel<128, 64, 16, false, false, true><<<MBLK, 128>>>(h3, Wg2, nullptr, u, N_NODES, D_O);
    cudaMemsetAsync(acc, 0, ACC_BYTES);
    edge_scatter_kernel<<<SCAT_BLOCKS, 256>>>(src, dst, u);
    finalize_kernel<<<FIN_BLOCKS, 256>>>(u, bg2, h4);

    // classifier
    classifier_kernel<<<(N_NODES + 255) / 256, 256>>>(h4, Wc, bc, logits);
}

// round 12
// speedup vs baseline: 1.6734x; 1.2127x over previous
#include <cuda_runtime.h>
#include <cuda_bf16.h>
#include <cstdint>

#define N_NODES 100000
#define E_EDGES 3200000
#define D_IN   512
#define D_H    128
#define D_O    64
#define NEG_SLOPE 0.01f

// ---------------- scratch (device globals; no allocation allowed) ----------------
__device__ __nv_bfloat16 g_h1 [N_NODES * D_H];   // 25.6 MB (bf16)
__device__ __nv_bfloat16 g_h2 [N_NODES * D_O];   // 12.8 MB (bf16)
__device__ __nv_bfloat16 g_h3 [N_NODES * D_O];   // 12.8 MB (bf16)
__device__ float g_u  [N_NODES * D_O];           // 25.6 MB
__device__ float g_acc[N_NODES * D_O];           // 25.6 MB
__device__ float g_deg [N_NODES];
__device__ float g_dinv[N_NODES];
__device__ __nv_bfloat16 g_w1t [D_H * D_IN];     // W1^T  [128][512] bf16 K-major
__device__ __nv_bfloat16 g_w2t [D_O * D_H];      // W2^T  [64][128]
__device__ __nv_bfloat16 g_wg1t[D_O * D_O];      // Wg1^T [64][64]
__device__ __nv_bfloat16 g_wg2t[D_O * D_O];      // Wg2^T [64][64]

__device__ __forceinline__ float lrelu(float v) {
    return v >= 0.0f ? v : NEG_SLOPE * v;
}

__device__ __forceinline__ uint32_t smem_u32(const void* p) {
    uint32_t a;
    asm("{ .reg .u64 t; cvta.to.shared.u64 t, %1; cvt.u32.u64 %0, t; }" : "=r"(a) : "l"(p));
    return a;
}
__device__ __forceinline__ uint32_t pack_bf16x2(float lo, float hi) {
    uint32_t r;
    asm("cvt.rn.satfinite.bf16x2.f32 %0, %1, %2;" : "=r"(r) : "f"(hi), "f"(lo));
    return r;
}
__device__ __forceinline__ void ldsm4(uint32_t& r0, uint32_t& r1, uint32_t& r2, uint32_t& r3,
                                      uint32_t addr) {
    asm volatile("ldmatrix.sync.aligned.m8n8.x4.shared.b16 {%0,%1,%2,%3}, [%4];"
                 : "=r"(r0), "=r"(r1), "=r"(r2), "=r"(r3) : "r"(addr));
}
__device__ __forceinline__ void mma_bf16(float* d, const uint32_t* a, const uint32_t* b) {
    asm volatile(
        "mma.sync.aligned.m16n8k16.row.col.f32.bf16.bf16.f32 "
        "{%0,%1,%2,%3}, {%4,%5,%6,%7}, {%8,%9}, {%0,%1,%2,%3};"
        : "+f"(d[0]), "+f"(d[1]), "+f"(d[2]), "+f"(d[3])
        : "r"(a[0]), "r"(a[1]), "r"(a[2]), "r"(a[3]), "r"(b[0]), "r"(b[1]));
}
// SW128 swizzle: XOR byte bits [6:4] with row bits [2:0] (128B rows)
#define SW128(o) ((o) ^ ((((uint32_t)(o)) >> 3) & 0x70))

// =====================================================================
// gemm1: bf16 HMMA GEMM  h1[M,128](bf16) = lrelu(A[M,512](f32) @ W1 + b1)
// BM=128 BN=128 BK=64, 256 threads = 8 warps (4 M x 2 N), warp tile 32x64.
// =====================================================================
__global__ __launch_bounds__(256) void gemm1_bf16_kernel(
    const float* __restrict__ A,
    const float* __restrict__ bias,
    __nv_bfloat16* __restrict__ C,
    int M)
{
    __shared__ __align__(1024) char smA[16384];   // 128 x 64 bf16, SW128
    __shared__ __align__(1024) char smB[16384];   // 128(n) x 64(k) bf16, SW128

    const int tid  = threadIdx.x;
    const int lane = tid & 31;
    const int warp = tid >> 5;
    const int warpM = warp & 3;
    const int warpN = warp >> 2;
    const int row0 = blockIdx.x * 128;

    const uint32_t baseA = smem_u32(smA);
    const uint32_t baseB = smem_u32(smB);
    const __nv_bfloat16* __restrict__ Bt = g_w1t;

    float acc[2][8][4];
#pragma unroll
    for (int m = 0; m < 2; m++)
#pragma unroll
        for (int n = 0; n < 8; n++)
#pragma unroll
            for (int v = 0; v < 4; v++) acc[m][n][v] = 0.0f;

    const int matid = lane >> 3;
    const int matrow = lane & 7;
    const int aRowOff = (matid & 1) * 8 + matrow;
    const int aColOff = (matid >> 1) * 16;
    const int bRowOff = (matid >> 1) * 8 + matrow;
    const int bColOff = (matid & 1) * 16;

    float4 pa[8];
    uint4  pb[4];

    auto g_load = [&](int k0) {
#pragma unroll
        for (int i = 0; i < 8; i++) {
            int li = tid + i * 256;
            int r  = li >> 4;
            int q  = li & 15;
            int gr = row0 + r;
            pa[i] = (gr < M) ? *(const float4*)&A[(size_t)gr * D_IN + k0 + q * 4]
                             : make_float4(0.f, 0.f, 0.f, 0.f);
        }
#pragma unroll
        for (int i = 0; i < 4; i++) {
            int li = tid + i * 256;
            int n  = li >> 3;
            int q  = li & 7;
            pb[i] = *(const uint4*)&Bt[(size_t)n * D_IN + k0 + q * 8];
        }
    };

    auto s_store = [&]() {
#pragma unroll
        for (int i = 0; i < 8; i++) {
            int li = tid + i * 256;
            int r  = li >> 4;
            int q  = li & 15;
            uint2 v;
            v.x = pack_bf16x2(pa[i].x, pa[i].y);
            v.y = pack_bf16x2(pa[i].z, pa[i].w);
            *(uint2*)&smA[SW128(r * 128 + q * 8)] = v;
        }
#pragma unroll
        for (int i = 0; i < 4; i++) {
            int li = tid + i * 256;
            int n  = li >> 3;
            int q  = li & 7;
            *(uint4*)&smB[SW128(n * 128 + q * 16)] = pb[i];
        }
    };

    auto compute = [&]() {
#pragma unroll
        for (int ks = 0; ks < 4; ks++) {
            const int kb = ks * 32;
            uint32_t af[2][4];
            uint32_t bf[8][2];
#pragma unroll
            for (int m = 0; m < 2; m++) {
                int row = warpM * 32 + m * 16 + aRowOff;
                ldsm4(af[m][0], af[m][1], af[m][2], af[m][3],
                      baseA + SW128(row * 128 + kb + aColOff));
            }
#pragma unroll
            for (int p = 0; p < 4; p++) {
                int row = warpN * 64 + p * 16 + bRowOff;
                ldsm4(bf[2 * p][0], bf[2 * p][1], bf[2 * p + 1][0], bf[2 * p + 1][1],
                      baseB + SW128(row * 128 + kb + bColOff));
            }
#pragma unroll
            for (int m = 0; m < 2; m++)
#pragma unroll
                for (int n = 0; n < 8; n++)
                    mma_bf16(acc[m][n], af[m], bf[n]);
        }
    };

    g_load(0);
    s_store();
    __syncthreads();
#pragma unroll 1
    for (int kt = 0; kt < 8; kt++) {
        if (kt + 1 < 8) g_load((kt + 1) * 64);
        compute();
        __syncthreads();
        if (kt + 1 < 8) {
            s_store();
            __syncthreads();
        }
    }

    // ---- epilogue: bias + lrelu, store bf16 ----
#pragma unroll
    for (int m = 0; m < 2; m++) {
        int rHi = row0 + warpM * 32 + m * 16 + (lane >> 2);
        int rLo = rHi + 8;
#pragma unroll
        for (int n = 0; n < 8; n++) {
            int col = warpN * 64 + n * 8 + (lane & 3) * 2;
            float b0 = bias[col], b1 = bias[col + 1];
            if (rHi < M)
                *(uint32_t*)&C[(size_t)rHi * D_H + col] =
                    pack_bf16x2(lrelu(acc[m][n][0] + b0), lrelu(acc[m][n][1] + b1));
            if (rLo < M)
                *(uint32_t*)&C[(size_t)rLo * D_H + col] =
                    pack_bf16x2(lrelu(acc[m][n][2] + b0), lrelu(acc[m][n][3] + b1));
        }
    }
}

// =====================================================================
// generic bf16 HMMA GEMM, BN=64: C[M,64] = op(A[M,K](bf16) @ Bt[64,K](bf16))
// BM=128 BK=64, 256 threads = 8 warps (4 M x 2 N), warp tile 32x32.
// =====================================================================
template<bool RELU, bool ADD_BIAS, bool SCALE_DINV, bool OUT_BF16>
__global__ __launch_bounds__(256) void gemm_bf16_n64_kernel(
    const __nv_bfloat16* __restrict__ A,
    const __nv_bfloat16* __restrict__ Bt,
    const float* __restrict__ bias,
    void* __restrict__ Cv,
    int M, int K)
{
    __shared__ __align__(1024) char smA[16384];   // 128 x 64 bf16, SW128
    __shared__ __align__(1024) char smB[8192];    // 64(n) x 64(k) bf16, SW128

    const int tid  = threadIdx.x;
    const int lane = tid & 31;
    const int warp = tid >> 5;
    const int warpM = warp & 3;
    const int warpN = warp >> 2;
    const int row0 = blockIdx.x * 128;

    const uint32_t baseA = smem_u32(smA);
    const uint32_t baseB = smem_u32(smB);

    float acc[2][4][4];
#pragma unroll
    for (int m = 0; m < 2; m++)
#pragma unroll
        for (int n = 0; n < 4; n++)
#pragma unroll
            for (int v = 0; v < 4; v++) acc[m][n][v] = 0.0f;

    const int matid = lane >> 3;
    const int matrow = lane & 7;
    const int aRowOff = (matid & 1) * 8 + matrow;
    const int aColOff = (matid >> 1) * 16;
    const int bRowOff = (matid >> 1) * 8 + matrow;
    const int bColOff = (matid & 1) * 16;

    uint4 pa[4], pb[2];

    auto g_load = [&](int k0) {
#pragma unroll
        for (int i = 0; i < 4; i++) {
            int li = tid + i * 256;          // 0..1023
            int r  = li >> 3;                // 0..127
            int q  = li & 7;                 // 16B chunk (8 bf16)
            int gr = row0 + r;
            pa[i] = (gr < M) ? *(const uint4*)&A[(size_t)gr * K + k0 + q * 8]
                             : make_uint4(0u, 0u, 0u, 0u);
        }
#pragma unroll
        for (int i = 0; i < 2; i++) {
            int li = tid + i * 256;          // 0..511
            int n  = li >> 3;                // 0..63
            int q  = li & 7;
            pb[i] = *(const uint4*)&Bt[(size_t)n * K + k0 + q * 8];
        }
    };

    auto s_store = [&]() {
#pragma unroll
        for (int i = 0; i < 4; i++) {
            int li = tid + i * 256;
            int r  = li >> 3;
            int q  = li & 7;
            *(uint4*)&smA[SW128(r * 128 + q * 16)] = pa[i];
        }
#pragma unroll
        for (int i = 0; i < 2; i++) {
            int li = tid + i * 256;
            int n  = li >> 3;
            int q  = li & 7;
            *(uint4*)&smB[SW128(n * 128 + q * 16)] = pb[i];
        }
    };

    auto compute = [&]() {
#pragma unroll
        for (int ks = 0; ks < 4; ks++) {
            const int kb = ks * 32;
            uint32_t af[2][4];
            uint32_t bf[4][2];
#pragma unroll
            for (int m = 0; m < 2; m++) {
                int row = warpM * 32 + m * 16 + aRowOff;
                ldsm4(af[m][0], af[m][1], af[m][2], af[m][3],
                      baseA + SW128(row * 128 + kb + aColOff));
            }
#pragma unroll
            for (int p = 0; p < 2; p++) {
                int row = warpN * 32 + p * 16 + bRowOff;
                ldsm4(bf[2 * p][0], bf[2 * p][1], bf[2 * p + 1][0], bf[2 * p + 1][1],
                      baseB + SW128(row * 128 + kb + bColOff));
            }
#pragma unroll
            for (int m = 0; m < 2; m++)
#pragma unroll
                for (int n = 0; n < 4; n++)
                    mma_bf16(acc[m][n], af[m], bf[n]);
        }
    };

    const int NT = K >> 6;                   // 1 or 2 K-tiles
    g_load(0);
    s_store();
    __syncthreads();
#pragma unroll 1
    for (int kt = 0; kt < NT; kt++) {
        if (kt + 1 < NT) g_load((kt + 1) * 64);
        compute();
        __syncthreads();
        if (kt + 1 < NT) {
            s_store();
            __syncthreads();
        }
    }

    // ---- epilogue ----
#pragma unroll
    for (int m = 0; m < 2; m++) {
        int rHi = row0 + warpM * 32 + m * 16 + (lane >> 2);
        int rLo = rHi + 8;
        float scHi = 1.0f, scLo = 1.0f;
        if (SCALE_DINV) {
            if (rHi < M) scHi = g_dinv[rHi];
            if (rLo < M) scLo = g_dinv[rLo];
        }
#pragma unroll
        for (int n = 0; n < 4; n++) {
            int col = warpN * 32 + n * 8 + (lane & 3) * 2;
            float b0 = 0.f, b1 = 0.f;
            if (ADD_BIAS) { b0 = bias[col]; b1 = bias[col + 1]; }
            float v0 = acc[m][n][0], v1 = acc[m][n][1];
            float v2 = acc[m][n][2], v3 = acc[m][n][3];
            if (ADD_BIAS) { v0 += b0; v1 += b1; v2 += b0; v3 += b1; }
            if (SCALE_DINV) { v0 *= scHi; v1 *= scHi; v2 *= scLo; v3 *= scLo; }
            if (RELU) { v0 = lrelu(v0); v1 = lrelu(v1); v2 = lrelu(v2); v3 = lrelu(v3); }
            if (OUT_BF16) {
                __nv_bfloat16* C = (__nv_bfloat16*)Cv;
                if (rHi < M) *(uint32_t*)&C[(size_t)rHi * D_O + col] = pack_bf16x2(v0, v1);
                if (rLo < M) *(uint32_t*)&C[(size_t)rLo * D_O + col] = pack_bf16x2(v2, v3);
            } else {
                float* C = (float*)Cv;
                if (rHi < M) { float2 f = {v0, v1}; *(float2*)&C[(size_t)rHi * D_O + col] = f; }
                if (rLo < M) { float2 f = {v2, v3}; *(float2*)&C[(size_t)rLo * D_O + col] = f; }
            }
        }
    }
}

// ---------------- weight transposes: all four weights -> bf16 K-major ----------------
__global__ void wprep_kernel(const float* __restrict__ W1,
                             const float* __restrict__ W2,
                             const float* __restrict__ Wg1,
                             const float* __restrict__ Wg2) {
    int idx = blockIdx.x * blockDim.x + threadIdx.x;
    if (idx < D_H * D_IN) {                               // W1t [128][512]
        int n = idx >> 9, k = idx & 511;
        g_w1t[idx] = __float2bfloat16(W1[k * D_H + n]);
    } else if (idx < D_H * D_IN + D_O * D_H) {            // W2t [64][128]
        int j = idx - D_H * D_IN;
        int n = j >> 7, k = j & 127;
        g_w2t[j] = __float2bfloat16(W2[k * D_O + n]);
    } else if (idx < D_H * D_IN + D_O * D_H + D_O * D_O) {// Wg1t [64][64]
        int j = idx - (D_H * D_IN + D_O * D_H);
        int n = j >> 6, k = j & 63;
        g_wg1t[j] = __float2bfloat16(Wg1[k * D_O + n]);
    } else if (idx < D_H * D_IN + D_O * D_H + 2 * D_O * D_O) {
        int j = idx - (D_H * D_IN + D_O * D_H + D_O * D_O);
        int n = j >> 6, k = j & 63;
        g_wg2t[j] = __float2bfloat16(Wg2[k * D_O + n]);
    }
}

// ---------------- degree / normalization ----------------
__global__ void init_deg_kernel() {
    int i = blockIdx.x * blockDim.x + threadIdx.x;
    if (i < N_NODES) g_deg[i] = 1.0f;           // self-loop
}

__global__ void count_deg_kernel(const int* __restrict__ dst) {
    int e = blockIdx.x * blockDim.x + threadIdx.x;
    if (e < E_EDGES) atomicAdd(&g_deg[dst[e]], 1.0f);
}

__global__ void calc_dinv_kernel() {
    int i = blockIdx.x * blockDim.x + threadIdx.x;
    if (i < N_NODES) g_dinv[i] = rsqrtf(g_deg[i]);   // deg >= 1 always
}

// ---------------- edge scatter: acc[d] += u[s]  (u already scaled by dinv[s]) ----------------
__global__ void edge_scatter_kernel(const int* __restrict__ src,
                                    const int* __restrict__ dst,
                                    const float* __restrict__ u) {
    long long idx = (long long)blockIdx.x * blockDim.x + threadIdx.x;
    if (idx >= (long long)E_EDGES * 16) return;
    int e = (int)(idx >> 4);
    int c = ((int)idx & 15) << 2;
    int s = __ldg(&src[e]);
    int d = __ldg(&dst[e]);
    float4 v = *(const float4*)&u[(long long)s * D_O + c];
    float* p = &g_acc[(long long)d * D_O + c];
    asm volatile("red.global.add.v4.f32 [%0], {%1,%2,%3,%4};"
                 :: "l"(p), "f"(v.x), "f"(v.y), "f"(v.z), "f"(v.w)
                 : "memory");
}

// ---------------- finalize: out = lrelu(dinv[n]*(acc[n] + u[n]) + b) ----------------
template<bool OUT_BF16>
__global__ void finalize_kernel(const float* __restrict__ u,
                                const float* __restrict__ bias,
                                void* __restrict__ outv) {
    int idx = blockIdx.x * blockDim.x + threadIdx.x;
    if (idx >= N_NODES * 16) return;
    int n = idx >> 4;
    int c = (idx & 15) << 2;
    float di = g_dinv[n];
    float4 a  = *(float4*)&g_acc[(long long)n * D_O + c];
    float4 uv = *(const float4*)&u[(long long)n * D_O + c];
    float4 b  = *(const float4*)&bias[c];
    a.x = lrelu(di * (a.x + uv.x) + b.x);
    a.y = lrelu(di * (a.y + uv.y) + b.y);
    a.z = lrelu(di * (a.z + uv.z) + b.z);
    a.w = lrelu(di * (a.w + uv.w) + b.w);
    if (OUT_BF16) {
        __nv_bfloat16* out = (__nv_bfloat16*)outv;
        uint2 v;
        v.x = pack_bf16x2(a.x, a.y);
        v.y = pack_bf16x2(a.z, a.w);
        *(uint2*)&out[(long long)n * D_O + c] = v;
    } else {
        float* out = (float*)outv;
        *(float4*)&out[(long long)n * D_O + c] = a;
    }
}

// ---------------- classifier: logits = h @ Wc + bc ----------------
__global__ void classifier_kernel(const float* __restrict__ h,
                                  const float* __restrict__ Wc,
                                  const float* __restrict__ bc,
                                  float* __restrict__ out) {
    __shared__ float w[D_O * 2];
    __shared__ float b2s[2];
    if (threadIdx.x < D_O * 2) w[threadIdx.x] = Wc[threadIdx.x];
    if (threadIdx.x < 2) b2s[threadIdx.x] = bc[threadIdx.x];
    __syncthreads();
    int n = blockIdx.x * blockDim.x + threadIdx.x;
    if (n >= N_NODES) return;
    float a0 = b2s[0], a1 = b2s[1];
    const float* hr = h + (long long)n * D_O;
#pragma unroll
    for (int k = 0; k < D_O; k++) {
        float v = hr[k];
        a0 += v * w[k * 2 + 0];
        a1 += v * w[k * 2 + 1];
    }
    out[n * 2 + 0] = a0;
    out[n * 2 + 1] = a1;
}

// ---------------- host launcher ----------------
extern "C" void kernel_launch(void* const* d_in, const int* in_sizes, int n_in,
                              void* d_out, int out_size) {
    const float* x   = (const float*)d_in[0];
    const int*   ei  = (const int*)  d_in[1];
    const float* W1  = (const float*)d_in[2];
    const float* b1  = (const float*)d_in[3];
    const float* W2  = (const float*)d_in[4];
    const float* b2  = (const float*)d_in[5];
    const float* Wg1 = (const float*)d_in[6];
    const float* bg1 = (const float*)d_in[7];
    const float* Wg2 = (const float*)d_in[8];
    const float* bg2 = (const float*)d_in[9];
    const float* Wc  = (const float*)d_in[10];
    const float* bc  = (const float*)d_in[11];
    float* out = (float*)d_out;

    const int* src = ei;
    const int* dst = ei + E_EDGES;

    __nv_bfloat16 *h1, *h2, *h3;
    float *u, *acc;
    __nv_bfloat16 *w1t, *w2t, *wg1t, *wg2t;
    cudaGetSymbolAddress((void**)&h1,  g_h1);
    cudaGetSymbolAddress((void**)&h2,  g_h2);
    cudaGetSymbolAddress((void**)&h3,  g_h3);
    cudaGetSymbolAddress((void**)&u,   g_u);
    cudaGetSymbolAddress((void**)&acc, g_acc);
    cudaGetSymbolAddress((void**)&w1t,  g_w1t);
    cudaGetSymbolAddress((void**)&w2t,  g_w2t);
    cudaGetSymbolAddress((void**)&wg1t, g_wg1t);
    cudaGetSymbolAddress((void**)&wg2t, g_wg2t);

    float* logits = out;                      // [N, 2]
    float* h4     = out + 2 * N_NODES;        // [N, 64]  (final h, also classifier input)

    const int MBLK = (N_NODES + 127) / 128;   // 782

    // degrees / symmetric norm first (gemm epilogues consume g_dinv)
    init_deg_kernel <<<(N_NODES + 255) / 256, 256>>>();
    count_deg_kernel<<<(E_EDGES + 255) / 256, 256>>>(dst);
    calc_dinv_kernel<<<(N_NODES + 255) / 256, 256>>>();

    // weights -> bf16 K-major (one kernel)
    const int WPREP = D_H * D_IN + D_O * D_H + 2 * D_O * D_O;   // 81920
    wprep_kernel<<<(WPREP + 255) / 256, 256>>>(W1, W2, Wg1, Wg2);

    // encoder (all bf16 HMMA)
    gemm1_bf16_kernel<<<MBLK, 256>>>(x, b1, h1, N_NODES);
    gemm_bf16_n64_kernel<true, true, false, true><<<MBLK, 256>>>(h1, w2t, b2, h2, N_NODES, D_H);

    const long long SCAT_THREADS = (long long)E_EDGES * 16;
    const int SCAT_BLOCKS = (int)((SCAT_THREADS + 255) / 256);
    const int FIN_BLOCKS  = (N_NODES * 16 + 255) / 256;
    const size_t ACC_BYTES = (size_t)N_NODES * D_O * sizeof(float);

    // GCN layer 1: u = (h2 @ Wg1)*dinv ; scatter ; h3 = lrelu(dinv*(acc+u)+bg1) (bf16)
    gemm_bf16_n64_kernel<false, false, true, false><<<MBLK, 256>>>(h2, wg1t, nullptr, u, N_NODES, D_O);
    cudaMemsetAsync(acc, 0, ACC_BYTES);
    edge_scatter_kernel<<<SCAT_BLOCKS, 256>>>(src, dst, u);
    finalize_kernel<true><<<FIN_BLOCKS, 256>>>(u, bg1, h3);

    // GCN layer 2 -> h4 (fp32) straight into d_out
    gemm_bf16_n64_kernel<false, false, true, false><<<MBLK, 256>>>(h3, wg2t, nullptr, u, N_NODES, D_O);
    cudaMemsetAsync(acc, 0, ACC_BYTES);
    edge_scatter_kernel<<<SCAT_BLOCKS, 256>>>(src, dst, u);
    finalize_kernel<false><<<FIN_BLOCKS, 256>>>(u, bg2, h4);

    // classifier
    classifier_kernel<<<(N_NODES + 255) / 256, 256>>>(h4, Wc, bc, logits);
}

// round 14
// speedup vs baseline: 1.7494x; 1.0454x over previous
#include <cuda_runtime.h>
#include <cuda_fp16.h>
#include <cstdint>

#define N_NODES 100000
#define E_EDGES 3200000
#define D_IN   512
#define D_H    128
#define D_O    64
#define NEG_SLOPE 0.01f

// ---------------- scratch (device globals; no allocation allowed) ----------------
__device__ __half g_h1 [N_NODES * D_H];   // 25.6 MB (fp16)
__device__ __half g_h2 [N_NODES * D_O];   // 12.8 MB
__device__ __half g_h3 [N_NODES * D_O];   // 12.8 MB
__device__ __half g_u  [N_NODES * D_O];   // 12.8 MB (fp16 messages; atomic acc stays fp32)
__device__ float  g_acc[N_NODES * D_O];   // 25.6 MB
__device__ float  g_deg [N_NODES];
__device__ float  g_dinv[N_NODES];
__device__ __half g_w1t [D_H * D_IN];     // W1^T  [128][512] fp16 K-major
__device__ __half g_w2t [D_O * D_H];      // W2^T  [64][128]
__device__ __half g_wg1t[D_O * D_O];      // Wg1^T [64][64]
__device__ __half g_wg2t[D_O * D_O];      // Wg2^T [64][64]

__device__ __forceinline__ float lrelu(float v) {
    return v >= 0.0f ? v : NEG_SLOPE * v;
}

__device__ __forceinline__ uint32_t smem_u32(const void* p) {
    uint32_t a;
    asm("{ .reg .u64 t; cvta.to.shared.u64 t, %1; cvt.u32.u64 %0, t; }" : "=r"(a) : "l"(p));
    return a;
}
// pack two f32 -> f16x2 (lo in lower half, hi in upper half)
__device__ __forceinline__ uint32_t pack_f16x2(float lo, float hi) {
    uint32_t r;
    asm("cvt.rn.f16x2.f32 %0, %1, %2;" : "=r"(r) : "f"(hi), "f"(lo));
    return r;
}
__device__ __forceinline__ void ldsm4(uint32_t& r0, uint32_t& r1, uint32_t& r2, uint32_t& r3,
                                      uint32_t addr) {
    asm volatile("ldmatrix.sync.aligned.m8n8.x4.shared.b16 {%0,%1,%2,%3}, [%4];"
                 : "=r"(r0), "=r"(r1), "=r"(r2), "=r"(r3) : "r"(addr));
}
__device__ __forceinline__ void mma_f16(float* d, const uint32_t* a, const uint32_t* b) {
    asm volatile(
        "mma.sync.aligned.m16n8k16.row.col.f32.f16.f16.f32 "
        "{%0,%1,%2,%3}, {%4,%5,%6,%7}, {%8,%9}, {%0,%1,%2,%3};"
        : "+f"(d[0]), "+f"(d[1]), "+f"(d[2]), "+f"(d[3])
        : "r"(a[0]), "r"(a[1]), "r"(a[2]), "r"(a[3]), "r"(b[0]), "r"(b[1]));
}
// SW128 swizzle: XOR byte bits [6:4] with row bits [2:0] (128B rows)
#define SW128(o) ((o) ^ ((((uint32_t)(o)) >> 3) & 0x70))

// =====================================================================
// gemm1: fp16 HMMA GEMM  h1[M,128](f16) = lrelu(A[M,512](f32) @ W1 + b1)
// BM=128 BN=128 BK=64, 256 threads = 8 warps (4 M x 2 N), warp tile 32x64.
// =====================================================================
__global__ __launch_bounds__(256) void gemm1_f16_kernel(
    const float* __restrict__ A,
    const float* __restrict__ bias,
    __half* __restrict__ C,
    int M)
{
    __shared__ __align__(1024) char smA[16384];   // 128 x 64 f16, SW128
    __shared__ __align__(1024) char smB[16384];   // 128(n) x 64(k) f16, SW128

    const int tid  = threadIdx.x;
    const int lane = tid & 31;
    const int warp = tid >> 5;
    const int warpM = warp & 3;
    const int warpN = warp >> 2;
    const int row0 = blockIdx.x * 128;

    const uint32_t baseA = smem_u32(smA);
    const uint32_t baseB = smem_u32(smB);
    const __half* __restrict__ Bt = g_w1t;

    float acc[2][8][4];
#pragma unroll
    for (int m = 0; m < 2; m++)
#pragma unroll
        for (int n = 0; n < 8; n++)
#pragma unroll
            for (int v = 0; v < 4; v++) acc[m][n][v] = 0.0f;

    const int matid = lane >> 3;
    const int matrow = lane & 7;
    const int aRowOff = (matid & 1) * 8 + matrow;
    const int aColOff = (matid >> 1) * 16;
    const int bRowOff = (matid >> 1) * 8 + matrow;
    const int bColOff = (matid & 1) * 16;

    float4 pa[8];
    uint4  pb[4];

    auto g_load = [&](int k0) {
#pragma unroll
        for (int i = 0; i < 8; i++) {
            int li = tid + i * 256;
            int r  = li >> 4;
            int q  = li & 15;
            int gr = row0 + r;
            pa[i] = (gr < M) ? *(const float4*)&A[(size_t)gr * D_IN + k0 + q * 4]
                             : make_float4(0.f, 0.f, 0.f, 0.f);
        }
#pragma unroll
        for (int i = 0; i < 4; i++) {
            int li = tid + i * 256;
            int n  = li >> 3;
            int q  = li & 7;
            pb[i] = *(const uint4*)&Bt[(size_t)n * D_IN + k0 + q * 8];
        }
    };

    auto s_store = [&]() {
#pragma unroll
        for (int i = 0; i < 8; i++) {
            int li = tid + i * 256;
            int r  = li >> 4;
            int q  = li & 15;
            uint2 v;
            v.x = pack_f16x2(pa[i].x, pa[i].y);
            v.y = pack_f16x2(pa[i].z, pa[i].w);
            *(uint2*)&smA[SW128(r * 128 + q * 8)] = v;
        }
#pragma unroll
        for (int i = 0; i < 4; i++) {
            int li = tid + i * 256;
            int n  = li >> 3;
            int q  = li & 7;
            *(uint4*)&smB[SW128(n * 128 + q * 16)] = pb[i];
        }
    };

    auto compute = [&]() {
#pragma unroll
        for (int ks = 0; ks < 4; ks++) {
            const int kb = ks * 32;
            uint32_t af[2][4];
            uint32_t bf[8][2];
#pragma unroll
            for (int m = 0; m < 2; m++) {
                int row = warpM * 32 + m * 16 + aRowOff;
                ldsm4(af[m][0], af[m][1], af[m][2], af[m][3],
                      baseA + SW128(row * 128 + kb + aColOff));
            }
#pragma unroll
            for (int p = 0; p < 4; p++) {
                int row = warpN * 64 + p * 16 + bRowOff;
                ldsm4(bf[2 * p][0], bf[2 * p][1], bf[2 * p + 1][0], bf[2 * p + 1][1],
                      baseB + SW128(row * 128 + kb + bColOff));
            }
#pragma unroll
            for (int m = 0; m < 2; m++)
#pragma unroll
                for (int n = 0; n < 8; n++)
                    mma_f16(acc[m][n], af[m], bf[n]);
        }
    };

    g_load(0);
    s_store();
    __syncthreads();
#pragma unroll 1
    for (int kt = 0; kt < 8; kt++) {
        if (kt + 1 < 8) g_load((kt + 1) * 64);
        compute();
        __syncthreads();
        if (kt + 1 < 8) {
            s_store();
            __syncthreads();
        }
    }

    // ---- epilogue: bias + lrelu, store fp16 ----
#pragma unroll
    for (int m = 0; m < 2; m++) {
        int rHi = row0 + warpM * 32 + m * 16 + (lane >> 2);
        int rLo = rHi + 8;
#pragma unroll
        for (int n = 0; n < 8; n++) {
            int col = warpN * 64 + n * 8 + (lane & 3) * 2;
            float b0 = bias[col], b1 = bias[col + 1];
            if (rHi < M)
                *(uint32_t*)&C[(size_t)rHi * D_H + col] =
                    pack_f16x2(lrelu(acc[m][n][0] + b0), lrelu(acc[m][n][1] + b1));
            if (rLo < M)
                *(uint32_t*)&C[(size_t)rLo * D_H + col] =
                    pack_f16x2(lrelu(acc[m][n][2] + b0), lrelu(acc[m][n][3] + b1));
        }
    }
}

// =====================================================================
// generic fp16 HMMA GEMM, BN=64: C[M,64](f16) = op(A[M,K](f16) @ Bt[64,K](f16))
// BM=128 BK=64, 256 threads = 8 warps (4 M x 2 N), warp tile 32x32.
// =====================================================================
template<bool RELU, bool ADD_BIAS, bool SCALE_DINV>
__global__ __launch_bounds__(256) void gemm_f16_n64_kernel(
    const __half* __restrict__ A,
    const __half* __restrict__ Bt,
    const float* __restrict__ bias,
    __half* __restrict__ C,
    int M, int K)
{
    __shared__ __align__(1024) char smA[16384];   // 128 x 64 f16, SW128
    __shared__ __align__(1024) char smB[8192];    // 64(n) x 64(k) f16, SW128

    const int tid  = threadIdx.x;
    const int lane = tid & 31;
    const int warp = tid >> 5;
    const int warpM = warp & 3;
    const int warpN = warp >> 2;
    const int row0 = blockIdx.x * 128;

    const uint32_t baseA = smem_u32(smA);
    const uint32_t baseB = smem_u32(smB);

    float acc[2][4][4];
#pragma unroll
    for (int m = 0; m < 2; m++)
#pragma unroll
        for (int n = 0; n < 4; n++)
#pragma unroll
            for (int v = 0; v < 4; v++) acc[m][n][v] = 0.0f;

    const int matid = lane >> 3;
    const int matrow = lane & 7;
    const int aRowOff = (matid & 1) * 8 + matrow;
    const int aColOff = (matid >> 1) * 16;
    const int bRowOff = (matid >> 1) * 8 + matrow;
    const int bColOff = (matid & 1) * 16;

    uint4 pa[4], pb[2];

    auto g_load = [&](int k0) {
#pragma unroll
        for (int i = 0; i < 4; i++) {
            int li = tid + i * 256;          // 0..1023
            int r  = li >> 3;                // 0..127
            int q  = li & 7;                 // 16B chunk (8 f16)
            int gr = row0 + r;
            pa[i] = (gr < M) ? *(const uint4*)&A[(size_t)gr * K + k0 + q * 8]
                             : make_uint4(0u, 0u, 0u, 0u);
        }
#pragma unroll
        for (int i = 0; i < 2; i++) {
            int li = tid + i * 256;          // 0..511
            int n  = li >> 3;                // 0..63
            int q  = li & 7;
            pb[i] = *(const uint4*)&Bt[(size_t)n * K + k0 + q * 8];
        }
    };

    auto s_store = [&]() {
#pragma unroll
        for (int i = 0; i < 4; i++) {
            int li = tid + i * 256;
            int r  = li >> 3;
            int q  = li & 7;
            *(uint4*)&smA[SW128(r * 128 + q * 16)] = pa[i];
        }
#pragma unroll
        for (int i = 0; i < 2; i++) {
            int li = tid + i * 256;
            int n  = li >> 3;
            int q  = li & 7;
            *(uint4*)&smB[SW128(n * 128 + q * 16)] = pb[i];
        }
    };

    auto compute = [&]() {
#pragma unroll
        for (int ks = 0; ks < 4; ks++) {
            const int kb = ks * 32;
            uint32_t af[2][4];
            uint32_t bf[4][2];
#pragma unroll
            for (int m = 0; m < 2; m++) {
                int row = warpM * 32 + m * 16 + aRowOff;
                ldsm4(af[m][0], af[m][1], af[m][2], af[m][3],
                      baseA + SW128(row * 128 + kb + aColOff));
            }
#pragma unroll
            for (int p = 0; p < 2; p++) {
                int row = warpN * 32 + p * 16 + bRowOff;
                ldsm4(bf[2 * p][0], bf[2 * p][1], bf[2 * p + 1][0], bf[2 * p + 1][1],
                      baseB + SW128(row * 128 + kb + bColOff));
            }
#pragma unroll
            for (int m = 0; m < 2; m++)
#pragma unroll
                for (int n = 0; n < 4; n++)
                    mma_f16(acc[m][n], af[m], bf[n]);
        }
    };

    const int NT = K >> 6;                   // 1 or 2 K-tiles
    g_load(0);
    s_store();
    __syncthreads();
#pragma unroll 1
    for (int kt = 0; kt < NT; kt++) {
        if (kt + 1 < NT) g_load((kt + 1) * 64);
        compute();
        __syncthreads();
        if (kt + 1 < NT) {
            s_store();
            __syncthreads();
        }
    }

    // ---- epilogue (always fp16 out) ----
#pragma unroll
    for (int m = 0; m < 2; m++) {
        int rHi = row0 + warpM * 32 + m * 16 + (lane >> 2);
        int rLo = rHi + 8;
        float scHi = 1.0f, scLo = 1.0f;
        if (SCALE_DINV) {
            if (rHi < M) scHi = g_dinv[rHi];
            if (rLo < M) scLo = g_dinv[rLo];
        }
#pragma unroll
        for (int n = 0; n < 4; n++) {
            int col = warpN * 32 + n * 8 + (lane & 3) * 2;
            float b0 = 0.f, b1 = 0.f;
            if (ADD_BIAS) { b0 = bias[col]; b1 = bias[col + 1]; }
            float v0 = acc[m][n][0], v1 = acc[m][n][1];
            float v2 = acc[m][n][2], v3 = acc[m][n][3];
            if (ADD_BIAS) { v0 += b0; v1 += b1; v2 += b0; v3 += b1; }
            if (SCALE_DINV) { v0 *= scHi; v1 *= scHi; v2 *= scLo; v3 *= scLo; }
            if (RELU) { v0 = lrelu(v0); v1 = lrelu(v1); v2 = lrelu(v2); v3 = lrelu(v3); }
            if (rHi < M) *(uint32_t*)&C[(size_t)rHi * D_O + col] = pack_f16x2(v0, v1);
            if (rLo < M) *(uint32_t*)&C[(size_t)rLo * D_O + col] = pack_f16x2(v2, v3);
        }
    }
}

// ---------------- weight transposes: all four weights -> fp16 K-major ----------------
__global__ void wprep_kernel(const float* __restrict__ W1,
                             const float* __restrict__ W2,
                             const float* __restrict__ Wg1,
                             const float* __restrict__ Wg2) {
    int idx = blockIdx.x * blockDim.x + threadIdx.x;
    if (idx < D_H * D_IN) {                               // W1t [128][512]
        int n = idx >> 9, k = idx & 511;
        g_w1t[idx] = __float2half(W1[k * D_H + n]);
    } else if (idx < D_H * D_IN + D_O * D_H) {            // W2t [64][128]
        int j = idx - D_H * D_IN;
        int n = j >> 7, k = j & 127;
        g_w2t[j] = __float2half(W2[k * D_O + n]);
    } else if (idx < D_H * D_IN + D_O * D_H + D_O * D_O) {// Wg1t [64][64]
        int j = idx - (D_H * D_IN + D_O * D_H);
        int n = j >> 6, k = j & 63;
        g_wg1t[j] = __float2half(Wg1[k * D_O + n]);
    } else if (idx < D_H * D_IN + D_O * D_H + 2 * D_O * D_O) {
        int j = idx - (D_H * D_IN + D_O * D_H + D_O * D_O);
        int n = j >> 6, k = j & 63;
        g_wg2t[j] = __float2half(Wg2[k * D_O + n]);
    }
}

// ---------------- degree / normalization ----------------
__global__ void init_deg_kernel() {
    int i = blockIdx.x * blockDim.x + threadIdx.x;
    if (i < N_NODES) g_deg[i] = 1.0f;           // self-loop
}

__global__ void count_deg_kernel(const int* __restrict__ dst) {
    int e = blockIdx.x * blockDim.x + threadIdx.x;
    if (e < E_EDGES) atomicAdd(&g_deg[dst[e]], 1.0f);
}

__global__ void calc_dinv_kernel() {
    int i = blockIdx.x * blockDim.x + threadIdx.x;
    if (i < N_NODES) g_dinv[i] = rsqrtf(g_deg[i]);   // deg >= 1 always
}

// ---------------- edge scatter: acc[d] += u[s]  (u fp16, acc fp32 atomics) ----------------
// one thread per (edge, 4-half chunk): 16 chunks of 4 halves per edge (8B gather each)
__global__ void edge_scatter_kernel(const int* __restrict__ src,
                                    const int* __restrict__ dst,
                                    const __half* __restrict__ u) {
    long long idx = (long long)blockIdx.x * blockDim.x + threadIdx.x;
    if (idx >= (long long)E_EDGES * 16) return;
    int e = (int)(idx >> 4);
    int c = ((int)idx & 15) << 2;
    int s = __ldg(&src[e]);
    int d = __ldg(&dst[e]);
    uint2 raw = *(const uint2*)&u[(size_t)s * D_O + c];
    float2 f0 = __half22float2(*(__half2*)&raw.x);
    float2 f1 = __half22float2(*(__half2*)&raw.y);
    float* p = &g_acc[(size_t)d * D_O + c];
    asm volatile("red.global.add.v4.f32 [%0], {%1,%2,%3,%4};"
                 :: "l"(p), "f"(f0.x), "f"(f0.y), "f"(f1.x), "f"(f1.y)
                 : "memory");
}

// ---------------- finalize: out = lrelu(dinv[n]*(acc[n] + u[n]) + b) ----------------
template<bool OUT_F16>
__global__ void finalize_kernel(const __half* __restrict__ u,
                                const float* __restrict__ bias,
                                void* __restrict__ outv) {
    int idx = blockIdx.x * blockDim.x + threadIdx.x;
    if (idx >= N_NODES * 16) return;
    int n = idx >> 4;
    int c = (idx & 15) << 2;
    float di = g_dinv[n];
    float4 a = *(float4*)&g_acc[(size_t)n * D_O + c];
    uint2 raw = *(const uint2*)&u[(size_t)n * D_O + c];
    float2 u0 = __half22float2(*(__half2*)&raw.x);
    float2 u1 = __half22float2(*(__half2*)&raw.y);
    float4 b = *(const float4*)&bias[c];
    a.x = lrelu(di * (a.x + u0.x) + b.x);
    a.y = lrelu(di * (a.y + u0.y) + b.y);
    a.z = lrelu(di * (a.z + u1.x) + b.z);
    a.w = lrelu(di * (a.w + u1.y) + b.w);
    if (OUT_F16) {
        __half* out = (__half*)outv;
        uint2 v;
        v.x = pack_f16x2(a.x, a.y);
        v.y = pack_f16x2(a.z, a.w);
        *(uint2*)&out[(size_t)n * D_O + c] = v;
    } else {
        float* out = (float*)outv;
        *(float4*)&out[(size_t)n * D_O + c] = a;
    }
}

// ---------------- classifier: logits = h @ Wc + bc ----------------
__global__ void classifier_kernel(const float* __restrict__ h,
                                  const float* __restrict__ Wc,
                                  const float* __restrict__ bc,
                                  float* __restrict__ out) {
    __shared__ float w[D_O * 2];
    __shared__ float b2s[2];
    if (threadIdx.x < D_O * 2) w[threadIdx.x] = Wc[threadIdx.x];
    if (threadIdx.x < 2) b2s[threadIdx.x] = bc[threadIdx.x];
    __syncthreads();
    int n = blockIdx.x * blockDim.x + threadIdx.x;
    if (n >= N_NODES) return;
    float a0 = b2s[0], a1 = b2s[1];
    const float* hr = h + (size_t)n * D_O;
#pragma unroll
    for (int k = 0; k < D_O; k++) {
        float v = hr[k];
        a0 += v * w[k * 2 + 0];
        a1 += v * w[k * 2 + 1];
    }
    out[n * 2 + 0] = a0;
    out[n * 2 + 1] = a1;
}

// ---------------- host launcher ----------------
extern "C" void kernel_launch(void* const* d_in, const int* in_sizes, int n_in,
                              void* d_out, int out_size) {
    const float* x   = (const float*)d_in[0];
    const int*   ei  = (const int*)  d_in[1];
    const float* W1  = (const float*)d_in[2];
    const float* b1  = (const float*)d_in[3];
    const float* W2  = (const float*)d_in[4];
    const float* b2  = (const float*)d_in[5];
    const float* Wg1 = (const float*)d_in[6];
    const float* bg1 = (const float*)d_in[7];
    const float* Wg2 = (const float*)d_in[8];
    const float* bg2 = (const float*)d_in[9];
    const float* Wc  = (const float*)d_in[10];
    const float* bc  = (const float*)d_in[11];
    float* out = (float*)d_out;

    const int* src = ei;
    const int* dst = ei + E_EDGES;

    __half *h1, *h2, *h3, *u;
    float *acc;
    __half *w1t, *w2t, *wg1t, *wg2t;
    cudaGetSymbolAddress((void**)&h1,  g_h1);
    cudaGetSymbolAddress((void**)&h2,  g_h2);
    cudaGetSymbolAddress((void**)&h3,  g_h3);
    cudaGetSymbolAddress((void**)&u,   g_u);
    cudaGetSymbolAddress((void**)&acc, g_acc);
    cudaGetSymbolAddress((void**)&w1t,  g_w1t);
    cudaGetSymbolAddress((void**)&w2t,  g_w2t);
    cudaGetSymbolAddress((void**)&wg1t, g_wg1t);
    cudaGetSymbolAddress((void**)&wg2t, g_wg2t);

    float* logits = out;                      // [N, 2]
    float* h4     = out + 2 * N_NODES;        // [N, 64]  (final h, also classifier input)

    const int MBLK = (N_NODES + 127) / 128;   // 782

    // degrees / symmetric norm first (gemm epilogues consume g_dinv)
    init_deg_kernel <<<(N_NODES + 255) / 256, 256>>>();
    count_deg_kernel<<<(E_EDGES + 255) / 256, 256>>>(dst);
    calc_dinv_kernel<<<(N_NODES + 255) / 256, 256>>>();

    // weights -> fp16 K-major (one kernel)
    const int WPREP = D_H * D_IN + D_O * D_H + 2 * D_O * D_O;   // 81920
    wprep_kernel<<<(WPREP + 255) / 256, 256>>>(W1, W2, Wg1, Wg2);

    // encoder (fp16 HMMA)
    gemm1_f16_kernel<<<MBLK, 256>>>(x, b1, h1, N_NODES);
    gemm_f16_n64_kernel<true, true, false><<<MBLK, 256>>>(h1, w2t, b2, h2, N_NODES, D_H);

    const long long SCAT_THREADS = (long long)E_EDGES * 16;
    const int SCAT_BLOCKS = (int)((SCAT_THREADS + 255) / 256);
    const int FIN_BLOCKS  = (N_NODES * 16 + 255) / 256;
    const size_t ACC_BYTES = (size_t)N_NODES * D_O * sizeof(float);

    // GCN layer 1: u = (h2 @ Wg1)*dinv (f16) ; scatter ; h3 = lrelu(dinv*(acc+u)+bg1) (f16)
    gemm_f16_n64_kernel<false, false, true><<<MBLK, 256>>>(h2, wg1t, nullptr, u, N_NODES, D_O);
    cudaMemsetAsync(acc, 0, ACC_BYTES);
    edge_scatter_kernel<<<SCAT_BLOCKS, 256>>>(src, dst, u);
    finalize_kernel<true><<<FIN_BLOCKS, 256>>>(u, bg1, h3);

    // GCN layer 2 -> h4 (fp32) straight into d_out
    gemm_f16_n64_kernel<false, false, true><<<MBLK, 256>>>(h3, wg2t, nullptr, u, N_NODES, D_O);
    cudaMemsetAsync(acc, 0, ACC_BYTES);
    edge_scatter_kernel<<<SCAT_BLOCKS, 256>>>(src, dst, u);
    finalize_kernel<false><<<FIN_BLOCKS, 256>>>(u, bg2, h4);

    // classifier
    classifier_kernel<<<(N_NODES + 255) / 256, 256>>>(h4, Wc, bc, logits);
}

// round 15
// speedup vs baseline: 2.7069x; 1.5473x over previous
#include <cuda_runtime.h>
#include <cuda_fp16.h>
#include <cstdint>

#define N_NODES 100000
#define E_EDGES 3200000
#define D_IN   512
#define D_H    128
#define D_O    64
#define NEG_SLOPE 0.01f
#define SCAN_BS 512
#define SCAN_NB ((N_NODES + SCAN_BS - 1) / SCAN_BS)   // 196

// ---------------- scratch (device globals; no allocation allowed) ----------------
__device__ __half g_h1 [N_NODES * D_H];   // 25.6 MB (fp16)
__device__ __half g_h2 [N_NODES * D_O];   // 12.8 MB
__device__ __half g_h3 [N_NODES * D_O];   // 12.8 MB
__device__ __half g_u  [N_NODES * D_O];   // 12.8 MB (fp16 messages)
__device__ int    g_degi [N_NODES];
__device__ float  g_dinv [N_NODES];
__device__ int    g_off  [N_NODES + 1];   // CSR offsets (by dst)
__device__ int    g_cursor[N_NODES];
__device__ int    g_bsum [SCAN_NB];
__device__ int    g_elist[E_EDGES];       // 12.8 MB source list grouped by dst
__device__ __half g_w1t [D_H * D_IN];     // W1^T  [128][512] fp16 K-major
__device__ __half g_w2t [D_O * D_H];      // W2^T  [64][128]
__device__ __half g_wg1t[D_O * D_O];      // Wg1^T [64][64]
__device__ __half g_wg2t[D_O * D_O];      // Wg2^T [64][64]

__device__ __forceinline__ float lrelu(float v) {
    return v >= 0.0f ? v : NEG_SLOPE * v;
}

__device__ __forceinline__ uint32_t smem_u32(const void* p) {
    uint32_t a;
    asm("{ .reg .u64 t; cvta.to.shared.u64 t, %1; cvt.u32.u64 %0, t; }" : "=r"(a) : "l"(p));
    return a;
}
// pack two f32 -> f16x2 (lo in lower half, hi in upper half)
__device__ __forceinline__ uint32_t pack_f16x2(float lo, float hi) {
    uint32_t r;
    asm("cvt.rn.f16x2.f32 %0, %1, %2;" : "=r"(r) : "f"(hi), "f"(lo));
    return r;
}
__device__ __forceinline__ void ldsm4(uint32_t& r0, uint32_t& r1, uint32_t& r2, uint32_t& r3,
                                      uint32_t addr) {
    asm volatile("ldmatrix.sync.aligned.m8n8.x4.shared.b16 {%0,%1,%2,%3}, [%4];"
                 : "=r"(r0), "=r"(r1), "=r"(r2), "=r"(r3) : "r"(addr));
}
__device__ __forceinline__ void mma_f16(float* d, const uint32_t* a, const uint32_t* b) {
    asm volatile(
        "mma.sync.aligned.m16n8k16.row.col.f32.f16.f16.f32 "
        "{%0,%1,%2,%3}, {%4,%5,%6,%7}, {%8,%9}, {%0,%1,%2,%3};"
        : "+f"(d[0]), "+f"(d[1]), "+f"(d[2]), "+f"(d[3])
        : "r"(a[0]), "r"(a[1]), "r"(a[2]), "r"(a[3]), "r"(b[0]), "r"(b[1]));
}
// SW128 swizzle: XOR byte bits [6:4] with row bits [2:0] (128B rows)
#define SW128(o) ((o) ^ ((((uint32_t)(o)) >> 3) & 0x70))

// =====================================================================
// gemm1: fp16 HMMA GEMM  h1[M,128](f16) = lrelu(A[M,512](f32) @ W1 + b1)
// =====================================================================
__global__ __launch_bounds__(256) void gemm1_f16_kernel(
    const float* __restrict__ A,
    const float* __restrict__ bias,
    __half* __restrict__ C,
    int M)
{
    __shared__ __align__(1024) char smA[16384];   // 128 x 64 f16, SW128
    __shared__ __align__(1024) char smB[16384];   // 128(n) x 64(k) f16, SW128

    const int tid  = threadIdx.x;
    const int lane = tid & 31;
    const int warp = tid >> 5;
    const int warpM = warp & 3;
    const int warpN = warp >> 2;
    const int row0 = blockIdx.x * 128;

    const uint32_t baseA = smem_u32(smA);
    const uint32_t baseB = smem_u32(smB);
    const __half* __restrict__ Bt = g_w1t;

    float acc[2][8][4];
#pragma unroll
    for (int m = 0; m < 2; m++)
#pragma unroll
        for (int n = 0; n < 8; n++)
#pragma unroll
            for (int v = 0; v < 4; v++) acc[m][n][v] = 0.0f;

    const int matid = lane >> 3;
    const int matrow = lane & 7;
    const int aRowOff = (matid & 1) * 8 + matrow;
    const int aColOff = (matid >> 1) * 16;
    const int bRowOff = (matid >> 1) * 8 + matrow;
    const int bColOff = (matid & 1) * 16;

    float4 pa[8];
    uint4  pb[4];

    auto g_load = [&](int k0) {
#pragma unroll
        for (int i = 0; i < 8; i++) {
            int li = tid + i * 256;
            int r  = li >> 4;
            int q  = li & 15;
            int gr = row0 + r;
            pa[i] = (gr < M) ? *(const float4*)&A[(size_t)gr * D_IN + k0 + q * 4]
                             : make_float4(0.f, 0.f, 0.f, 0.f);
        }
#pragma unroll
        for (int i = 0; i < 4; i++) {
            int li = tid + i * 256;
            int n  = li >> 3;
            int q  = li & 7;
            pb[i] = *(const uint4*)&Bt[(size_t)n * D_IN + k0 + q * 8];
        }
    };

    auto s_store = [&]() {
#pragma unroll
        for (int i = 0; i < 8; i++) {
            int li = tid + i * 256;
            int r  = li >> 4;
            int q  = li & 15;
            uint2 v;
            v.x = pack_f16x2(pa[i].x, pa[i].y);
            v.y = pack_f16x2(pa[i].z, pa[i].w);
            *(uint2*)&smA[SW128(r * 128 + q * 8)] = v;
        }
#pragma unroll
        for (int i = 0; i < 4; i++) {
            int li = tid + i * 256;
            int n  = li >> 3;
            int q  = li & 7;
            *(uint4*)&smB[SW128(n * 128 + q * 16)] = pb[i];
        }
    };

    auto compute = [&]() {
#pragma unroll
        for (int ks = 0; ks < 4; ks++) {
            const int kb = ks * 32;
            uint32_t af[2][4];
            uint32_t bf[8][2];
#pragma unroll
            for (int m = 0; m < 2; m++) {
                int row = warpM * 32 + m * 16 + aRowOff;
                ldsm4(af[m][0], af[m][1], af[m][2], af[m][3],
                      baseA + SW128(row * 128 + kb + aColOff));
            }
#pragma unroll
            for (int p = 0; p < 4; p++) {
                int row = warpN * 64 + p * 16 + bRowOff;
                ldsm4(bf[2 * p][0], bf[2 * p][1], bf[2 * p + 1][0], bf[2 * p + 1][1],
                      baseB + SW128(row * 128 + kb + bColOff));
            }
#pragma unroll
            for (int m = 0; m < 2; m++)
#pragma unroll
                for (int n = 0; n < 8; n++)
                    mma_f16(acc[m][n], af[m], bf[n]);
        }
    };

    g_load(0);
    s_store();
    __syncthreads();
#pragma unroll 1
    for (int kt = 0; kt < 8; kt++) {
        if (kt + 1 < 8) g_load((kt + 1) * 64);
        compute();
        __syncthreads();
        if (kt + 1 < 8) {
            s_store();
            __syncthreads();
        }
    }

#pragma unroll
    for (int m = 0; m < 2; m++) {
        int rHi = row0 + warpM * 32 + m * 16 + (lane >> 2);
        int rLo = rHi + 8;
#pragma unroll
        for (int n = 0; n < 8; n++) {
            int col = warpN * 64 + n * 8 + (lane & 3) * 2;
            float b0 = bias[col], b1 = bias[col + 1];
            if (rHi < M)
                *(uint32_t*)&C[(size_t)rHi * D_H + col] =
                    pack_f16x2(lrelu(acc[m][n][0] + b0), lrelu(acc[m][n][1] + b1));
            if (rLo < M)
                *(uint32_t*)&C[(size_t)rLo * D_H + col] =
                    pack_f16x2(lrelu(acc[m][n][2] + b0), lrelu(acc[m][n][3] + b1));
        }
    }
}

// =====================================================================
// generic fp16 HMMA GEMM, BN=64 (same as R14 passing version)
// =====================================================================
template<bool RELU, bool ADD_BIAS, bool SCALE_DINV>
__global__ __launch_bounds__(256) void gemm_f16_n64_kernel(
    const __half* __restrict__ A,
    const __half* __restrict__ Bt,
    const float* __restrict__ bias,
    __half* __restrict__ C,
    int M, int K)
{
    __shared__ __align__(1024) char smA[16384];
    __shared__ __align__(1024) char smB[8192];

    const int tid  = threadIdx.x;
    const int lane = tid & 31;
    const int warp = tid >> 5;
    const int warpM = warp & 3;
    const int warpN = warp >> 2;
    const int row0 = blockIdx.x * 128;

    const uint32_t baseA = smem_u32(smA);
    const uint32_t baseB = smem_u32(smB);

    float acc[2][4][4];
#pragma unroll
    for (int m = 0; m < 2; m++)
#pragma unroll
        for (int n = 0; n < 4; n++)
#pragma unroll
            for (int v = 0; v < 4; v++) acc[m][n][v] = 0.0f;

    const int matid = lane >> 3;
    const int matrow = lane & 7;
    const int aRowOff = (matid & 1) * 8 + matrow;
    const int aColOff = (matid >> 1) * 16;
    const int bRowOff = (matid >> 1) * 8 + matrow;
    const int bColOff = (matid & 1) * 16;

    uint4 pa[4], pb[2];

    auto g_load = [&](int k0) {
#pragma unroll
        for (int i = 0; i < 4; i++) {
            int li = tid + i * 256;
            int r  = li >> 3;
            int q  = li & 7;
            int gr = row0 + r;
            pa[i] = (gr < M) ? *(const uint4*)&A[(size_t)gr * K + k0 + q * 8]
                             : make_uint4(0u, 0u, 0u, 0u);
        }
#pragma unroll
        for (int i = 0; i < 2; i++) {
            int li = tid + i * 256;
            int n  = li >> 3;
            int q  = li & 7;
            pb[i] = *(const uint4*)&Bt[(size_t)n * K + k0 + q * 8];
        }
    };

    auto s_store = [&]() {
#pragma unroll
        for (int i = 0; i < 4; i++) {
            int li = tid + i * 256;
            int r  = li >> 3;
            int q  = li & 7;
            *(uint4*)&smA[SW128(r * 128 + q * 16)] = pa[i];
        }
#pragma unroll
        for (int i = 0; i < 2; i++) {
            int li = tid + i * 256;
            int n  = li >> 3;
            int q  = li & 7;
            *(uint4*)&smB[SW128(n * 128 + q * 16)] = pb[i];
        }
    };

    auto compute = [&]() {
#pragma unroll
        for (int ks = 0; ks < 4; ks++) {
            const int kb = ks * 32;
            uint32_t af[2][4];
            uint32_t bf[4][2];
#pragma unroll
            for (int m = 0; m < 2; m++) {
                int row = warpM * 32 + m * 16 + aRowOff;
                ldsm4(af[m][0], af[m][1], af[m][2], af[m][3],
                      baseA + SW128(row * 128 + kb + aColOff));
            }
#pragma unroll
            for (int p = 0; p < 2; p++) {
                int row = warpN * 32 + p * 16 + bRowOff;
                ldsm4(bf[2 * p][0], bf[2 * p][1], bf[2 * p + 1][0], bf[2 * p + 1][1],
                      baseB + SW128(row * 128 + kb + bColOff));
            }
#pragma unroll
            for (int m = 0; m < 2; m++)
#pragma unroll
                for (int n = 0; n < 4; n++)
                    mma_f16(acc[m][n], af[m], bf[n]);
        }
    };

    const int NT = K >> 6;
    g_load(0);
    s_store();
    __syncthreads();
#pragma unroll 1
    for (int kt = 0; kt < NT; kt++) {
        if (kt + 1 < NT) g_load((kt + 1) * 64);
        compute();
        __syncthreads();
        if (kt + 1 < NT) {
            s_store();
            __syncthreads();
        }
    }

#pragma unroll
    for (int m = 0; m < 2; m++) {
        int rHi = row0 + warpM * 32 + m * 16 + (lane >> 2);
        int rLo = rHi + 8;
        float scHi = 1.0f, scLo = 1.0f;
        if (SCALE_DINV) {
            if (rHi < M) scHi = g_dinv[rHi];
            if (rLo < M) scLo = g_dinv[rLo];
        }
#pragma unroll
        for (int n = 0; n < 4; n++) {
            int col = warpN * 32 + n * 8 + (lane & 3) * 2;
            float b0 = 0.f, b1 = 0.f;
            if (ADD_BIAS) { b0 = bias[col]; b1 = bias[col + 1]; }
            float v0 = acc[m][n][0], v1 = acc[m][n][1];
            float v2 = acc[m][n][2], v3 = acc[m][n][3];
            if (ADD_BIAS) { v0 += b0; v1 += b1; v2 += b0; v3 += b1; }
            if (SCALE_DINV) { v0 *= scHi; v1 *= scHi; v2 *= scLo; v3 *= scLo; }
            if (RELU) { v0 = lrelu(v0); v1 = lrelu(v1); v2 = lrelu(v2); v3 = lrelu(v3); }
            if (rHi < M) *(uint32_t*)&C[(size_t)rHi * D_O + col] = pack_f16x2(v0, v1);
            if (rLo < M) *(uint32_t*)&C[(size_t)rLo * D_O + col] = pack_f16x2(v2, v3);
        }
    }
}

// ---------------- weight transposes: all four weights -> fp16 K-major ----------------
__global__ void wprep_kernel(const float* __restrict__ W1,
                             const float* __restrict__ W2,
                             const float* __restrict__ Wg1,
                             const float* __restrict__ Wg2) {
    int idx = blockIdx.x * blockDim.x + threadIdx.x;
    if (idx < D_H * D_IN) {
        int n = idx >> 9, k = idx & 511;
        g_w1t[idx] = __float2half(W1[k * D_H + n]);
    } else if (idx < D_H * D_IN + D_O * D_H) {
        int j = idx - D_H * D_IN;
        int n = j >> 7, k = j & 127;
        g_w2t[j] = __float2half(W2[k * D_O + n]);
    } else if (idx < D_H * D_IN + D_O * D_H + D_O * D_O) {
        int j = idx - (D_H * D_IN + D_O * D_H);
        int n = j >> 6, k = j & 63;
        g_wg1t[j] = __float2half(Wg1[k * D_O + n]);
    } else if (idx < D_H * D_IN + D_O * D_H + 2 * D_O * D_O) {
        int j = idx - (D_H * D_IN + D_O * D_H + D_O * D_O);
        int n = j >> 6, k = j & 63;
        g_wg2t[j] = __float2half(Wg2[k * D_O + n]);
    }
}

// ---------------- degree count (int) + dinv ----------------
__global__ void count_deg_kernel(const int* __restrict__ dst) {
    int e = blockIdx.x * blockDim.x + threadIdx.x;
    if (e < E_EDGES) atomicAdd(&g_degi[dst[e]], 1);
}

__global__ void calc_dinv_kernel() {
    int i = blockIdx.x * blockDim.x + threadIdx.x;
    if (i < N_NODES) g_dinv[i] = rsqrtf(1.0f + (float)g_degi[i]);   // +1 self-loop
}

// ---------------- CSR build: exclusive scan of degrees + fill ----------------
__global__ void scan1_kernel() {
    __shared__ int sm[SCAN_BS];
    int i = blockIdx.x * SCAN_BS + threadIdx.x;
    int v = (i < N_NODES) ? g_degi[i] : 0;
    sm[threadIdx.x] = v;
    __syncthreads();
#pragma unroll
    for (int off = 1; off < SCAN_BS; off <<= 1) {
        int t = (threadIdx.x >= off) ? sm[threadIdx.x - off] : 0;
        __syncthreads();
        sm[threadIdx.x] += t;
        __syncthreads();
    }
    if (i < N_NODES) g_off[i] = sm[threadIdx.x] - v;       // block-local exclusive
    if (threadIdx.x == SCAN_BS - 1) g_bsum[blockIdx.x] = sm[threadIdx.x];
}

__global__ void scan2_kernel() {      // 1 block, 256 threads; SCAN_NB=196 <= 256
    __shared__ int sm[256];
    int v = (threadIdx.x < SCAN_NB) ? g_bsum[threadIdx.x] : 0;
    sm[threadIdx.x] = v;
    __syncthreads();
#pragma unroll
    for (int off = 1; off < 256; off <<= 1) {
        int t = (threadIdx.x >= off) ? sm[threadIdx.x - off] : 0;
        __syncthreads();
        sm[threadIdx.x] += t;
        __syncthreads();
    }
    if (threadIdx.x < SCAN_NB) g_bsum[threadIdx.x] = sm[threadIdx.x] - v;  // exclusive
    if (threadIdx.x == 255) g_off[N_NODES] = sm[255];       // total = E_EDGES
}

__global__ void scan3_kernel() {
    int i = blockIdx.x * blockDim.x + threadIdx.x;
    if (i < N_NODES) {
        int o = g_off[i] + g_bsum[i / SCAN_BS];
        g_off[i] = o;
        g_cursor[i] = o;
    }
}

__global__ void fill_kernel(const int* __restrict__ src, const int* __restrict__ dst) {
    int e = blockIdx.x * blockDim.x + threadIdx.x;
    if (e < E_EDGES) {
        int p = atomicAdd(&g_cursor[dst[e]], 1);
        g_elist[p] = src[e];
    }
}

// ---------------- gather: warp per node ----------------
// out[d] = lrelu(dinv[d] * (sum_{e:dst=d} u[src[e]] + u[d]) + bias)
template<bool OUT_F16>
__global__ __launch_bounds__(256) void gather_kernel(
    const __half* __restrict__ u,
    const float* __restrict__ bias,
    void* __restrict__ outv)
{
    int gw = (blockIdx.x * blockDim.x + threadIdx.x) >> 5;   // warp id = node
    int lane = threadIdx.x & 31;
    if (gw >= N_NODES) return;
    const int d = gw;
    const int beg = g_off[d];
    const int end = g_off[d + 1];

    float a0 = 0.0f, a1 = 0.0f;
    for (int base = beg; base < end; base += 32) {
        int idx = base + lane;
        int srcv = (idx < end) ? g_elist[idx] : 0;
        int n = min(32, end - base);
        int j = 0;
        for (; j + 4 <= n; j += 4) {
            int s0 = __shfl_sync(0xffffffffu, srcv, j);
            int s1 = __shfl_sync(0xffffffffu, srcv, j + 1);
            int s2 = __shfl_sync(0xffffffffu, srcv, j + 2);
            int s3 = __shfl_sync(0xffffffffu, srcv, j + 3);
            uint32_t r0 = *(const uint32_t*)&u[(size_t)s0 * D_O + lane * 2];
            uint32_t r1 = *(const uint32_t*)&u[(size_t)s1 * D_O + lane * 2];
            uint32_t r2 = *(const uint32_t*)&u[(size_t)s2 * D_O + lane * 2];
            uint32_t r3 = *(const uint32_t*)&u[(size_t)s3 * D_O + lane * 2];
            float2 f0 = __half22float2(*(__half2*)&r0);
            float2 f1 = __half22float2(*(__half2*)&r1);
            float2 f2 = __half22float2(*(__half2*)&r2);
            float2 f3 = __half22float2(*(__half2*)&r3);
            a0 += (f0.x + f1.x) + (f2.x + f3.x);
            a1 += (f0.y + f1.y) + (f2.y + f3.y);
        }
        for (; j < n; j++) {
            int s = __shfl_sync(0xffffffffu, srcv, j);
            uint32_t r = *(const uint32_t*)&u[(size_t)s * D_O + lane * 2];
            float2 f = __half22float2(*(__half2*)&r);
            a0 += f.x;
            a1 += f.y;
        }
    }
    // self-loop term
    {
        uint32_t r = *(const uint32_t*)&u[(size_t)d * D_O + lane * 2];
        float2 f = __half22float2(*(__half2*)&r);
        a0 += f.x;
        a1 += f.y;
    }
    float di = g_dinv[d];
    float b0 = bias[lane * 2], b1 = bias[lane * 2 + 1];
    float v0 = lrelu(di * a0 + b0);
    float v1 = lrelu(di * a1 + b1);
    if (OUT_F16) {
        __half* out = (__half*)outv;
        *(uint32_t*)&out[(size_t)d * D_O + lane * 2] = pack_f16x2(v0, v1);
    } else {
        float* out = (float*)outv;
        float2 f = {v0, v1};
        *(float2*)&out[(size_t)d * D_O + lane * 2] = f;
    }
}

// ---------------- classifier: logits = h @ Wc + bc ----------------
__global__ void classifier_kernel(const float* __restrict__ h,
                                  const float* __restrict__ Wc,
                                  const float* __restrict__ bc,
                                  float* __restrict__ out) {
    __shared__ float w[D_O * 2];
    __shared__ float b2s[2];
    if (threadIdx.x < D_O * 2) w[threadIdx.x] = Wc[threadIdx.x];
    if (threadIdx.x < 2) b2s[threadIdx.x] = bc[threadIdx.x];
    __syncthreads();
    int n = blockIdx.x * blockDim.x + threadIdx.x;
    if (n >= N_NODES) return;
    float a0 = b2s[0], a1 = b2s[1];
    const float* hr = h + (size_t)n * D_O;
#pragma unroll
    for (int k = 0; k < D_O; k++) {
        float v = hr[k];
        a0 += v * w[k * 2 + 0];
        a1 += v * w[k * 2 + 1];
    }
    out[n * 2 + 0] = a0;
    out[n * 2 + 1] = a1;
}

// ---------------- host launcher ----------------
extern "C" void kernel_launch(void* const* d_in, const int* in_sizes, int n_in,
                              void* d_out, int out_size) {
    const float* x   = (const float*)d_in[0];
    const int*   ei  = (const int*)  d_in[1];
    const float* W1  = (const float*)d_in[2];
    const float* b1  = (const float*)d_in[3];
    const float* W2  = (const float*)d_in[4];
    const float* b2  = (const float*)d_in[5];
    const float* Wg1 = (const float*)d_in[6];
    const float* bg1 = (const float*)d_in[7];
    const float* Wg2 = (const float*)d_in[8];
    const float* bg2 = (const float*)d_in[9];
    const float* Wc  = (const float*)d_in[10];
    const float* bc  = (const float*)d_in[11];
    float* out = (float*)d_out;

    const int* src = ei;
    const int* dst = ei + E_EDGES;

    __half *h1, *h2, *h3, *u;
    int* degi;
    cudaGetSymbolAddress((void**)&h1,   g_h1);
    cudaGetSymbolAddress((void**)&h2,   g_h2);
    cudaGetSymbolAddress((void**)&h3,   g_h3);
    cudaGetSymbolAddress((void**)&u,    g_u);
    cudaGetSymbolAddress((void**)&degi, g_degi);

    __half *w2t, *wg1t, *wg2t;
    cudaGetSymbolAddress((void**)&w2t,  g_w2t);
    cudaGetSymbolAddress((void**)&wg1t, g_wg1t);
    cudaGetSymbolAddress((void**)&wg2t, g_wg2t);

    float* logits = out;                      // [N, 2]
    float* h4     = out + 2 * N_NODES;        // [N, 64]

    const int MBLK = (N_NODES + 127) / 128;   // 782

    // ---- CSR build (shared by both GCN layers) ----
    cudaMemsetAsync(degi, 0, N_NODES * sizeof(int));
    count_deg_kernel<<<(E_EDGES + 255) / 256, 256>>>(dst);
    calc_dinv_kernel<<<(N_NODES + 255) / 256, 256>>>();
    scan1_kernel<<<SCAN_NB, SCAN_BS>>>();
    scan2_kernel<<<1, 256>>>();
    scan3_kernel<<<(N_NODES + 255) / 256, 256>>>();
    fill_kernel<<<(E_EDGES + 255) / 256, 256>>>(src, dst);

    // ---- weights -> fp16 K-major ----
    const int WPREP = D_H * D_IN + D_O * D_H + 2 * D_O * D_O;   // 81920
    wprep_kernel<<<(WPREP + 255) / 256, 256>>>(W1, W2, Wg1, Wg2);

    // ---- encoder (fp16 HMMA) ----
    gemm1_f16_kernel<<<MBLK, 256>>>(x, b1, h1, N_NODES);
    gemm_f16_n64_kernel<true, true, false><<<MBLK, 256>>>(h1, w2t, b2, h2, N_NODES, D_H);

    const int GATHER_BLOCKS = (N_NODES * 32 + 255) / 256;   // 12500

    // ---- GCN layer 1: u = (h2 @ Wg1)*dinv ; gather -> h3 (f16) ----
    gemm_f16_n64_kernel<false, false, true><<<MBLK, 256>>>(h2, wg1t, nullptr, u, N_NODES, D_O);
    gather_kernel<true><<<GATHER_BLOCKS, 256>>>(u, bg1, h3);

    // ---- GCN layer 2: u = (h3 @ Wg2)*dinv ; gather -> h4 (f32, straight into d_out) ----
    gemm_f16_n64_kernel<false, false, true><<<MBLK, 256>>>(h3, wg2t, nullptr, u, N_NODES, D_O);
    gather_kernel<false><<<GATHER_BLOCKS, 256>>>(u, bg2, (void*)h4);

    // ---- classifier ----
    classifier_kernel<<<(N_NODES + 255) / 256, 256>>>(h4, Wc, bc, logits);
}

// round 16
// speedup vs baseline: 2.9329x; 1.0835x over previous
#include <cuda_runtime.h>
#include <cuda_fp16.h>
#include <cstdint>

#define N_NODES 100000
#define E_EDGES 3200000
#define D_IN   512
#define D_H    128
#define D_O    64
#define NEG_SLOPE 0.01f
#define SCAN_BS 512
#define SCAN_NB ((N_NODES + SCAN_BS - 1) / SCAN_BS)   // 196

// ---------------- scratch (device globals; no allocation allowed) ----------------
__device__ __half g_h1 [N_NODES * D_H];   // 25.6 MB (fp16)
__device__ __half g_h2 [N_NODES * D_O];   // 12.8 MB
__device__ __half g_h3 [N_NODES * D_O];   // 12.8 MB
__device__ __half g_u  [N_NODES * D_O];   // 12.8 MB (fp16 messages)
__device__ int    g_degi [N_NODES];
__device__ float  g_dinv [N_NODES];
__device__ int    g_off  [N_NODES + 1];   // CSR offsets (by dst)
__device__ int    g_cursor[N_NODES];
__device__ int    g_bsum [SCAN_NB];
__device__ int    g_elist[E_EDGES];       // 12.8 MB source list grouped by dst
__device__ __half g_w1t [D_H * D_IN];     // W1^T  [128][512] fp16 K-major
__device__ __half g_w2t [D_O * D_H];      // W2^T  [64][128]
__device__ __half g_wg1t[D_O * D_O];      // Wg1^T [64][64]
__device__ __half g_wg2t[D_O * D_O];      // Wg2^T [64][64]

__device__ __forceinline__ float lrelu(float v) {
    return v >= 0.0f ? v : NEG_SLOPE * v;
}

__device__ __forceinline__ uint32_t smem_u32(const void* p) {
    uint32_t a;
    asm("{ .reg .u64 t; cvta.to.shared.u64 t, %1; cvt.u32.u64 %0, t; }" : "=r"(a) : "l"(p));
    return a;
}
// pack two f32 -> f16x2 (lo in lower half, hi in upper half)
__device__ __forceinline__ uint32_t pack_f16x2(float lo, float hi) {
    uint32_t r;
    asm("cvt.rn.f16x2.f32 %0, %1, %2;" : "=r"(r) : "f"(hi), "f"(lo));
    return r;
}
__device__ __forceinline__ void ldsm4(uint32_t& r0, uint32_t& r1, uint32_t& r2, uint32_t& r3,
                                      uint32_t addr) {
    asm volatile("ldmatrix.sync.aligned.m8n8.x4.shared.b16 {%0,%1,%2,%3}, [%4];"
                 : "=r"(r0), "=r"(r1), "=r"(r2), "=r"(r3) : "r"(addr));
}
__device__ __forceinline__ void mma_f16(float* d, const uint32_t* a, const uint32_t* b) {
    asm volatile(
        "mma.sync.aligned.m16n8k16.row.col.f32.f16.f16.f32 "
        "{%0,%1,%2,%3}, {%4,%5,%6,%7}, {%8,%9}, {%0,%1,%2,%3};"
        : "+f"(d[0]), "+f"(d[1]), "+f"(d[2]), "+f"(d[3])
        : "r"(a[0]), "r"(a[1]), "r"(a[2]), "r"(a[3]), "r"(b[0]), "r"(b[1]));
}
// SW128 swizzle: XOR byte bits [6:4] with row bits [2:0] (128B rows)
#define SW128(o) ((o) ^ ((((uint32_t)(o)) >> 3) & 0x70))

// =====================================================================
// gemm1: fp16 HMMA GEMM  h1[M,128](f16) = lrelu(A[M,512](f32) @ W1 + b1)
// =====================================================================
__global__ __launch_bounds__(256) void gemm1_f16_kernel(
    const float* __restrict__ A,
    const float* __restrict__ bias,
    __half* __restrict__ C,
    int M)
{
    __shared__ __align__(1024) char smA[16384];   // 128 x 64 f16, SW128
    __shared__ __align__(1024) char smB[16384];   // 128(n) x 64(k) f16, SW128

    const int tid  = threadIdx.x;
    const int lane = tid & 31;
    const int warp = tid >> 5;
    const int warpM = warp & 3;
    const int warpN = warp >> 2;
    const int row0 = blockIdx.x * 128;

    const uint32_t baseA = smem_u32(smA);
    const uint32_t baseB = smem_u32(smB);
    const __half* __restrict__ Bt = g_w1t;

    float acc[2][8][4];
#pragma unroll
    for (int m = 0; m < 2; m++)
#pragma unroll
        for (int n = 0; n < 8; n++)
#pragma unroll
            for (int v = 0; v < 4; v++) acc[m][n][v] = 0.0f;

    const int matid = lane >> 3;
    const int matrow = lane & 7;
    const int aRowOff = (matid & 1) * 8 + matrow;
    const int aColOff = (matid >> 1) * 16;
    const int bRowOff = (matid >> 1) * 8 + matrow;
    const int bColOff = (matid & 1) * 16;

    float4 pa[8];
    uint4  pb[4];

    auto g_load = [&](int k0) {
#pragma unroll
        for (int i = 0; i < 8; i++) {
            int li = tid + i * 256;
            int r  = li >> 4;
            int q  = li & 15;
            int gr = row0 + r;
            pa[i] = (gr < M) ? *(const float4*)&A[(size_t)gr * D_IN + k0 + q * 4]
                             : make_float4(0.f, 0.f, 0.f, 0.f);
        }
#pragma unroll
        for (int i = 0; i < 4; i++) {
            int li = tid + i * 256;
            int n  = li >> 3;
            int q  = li & 7;
            pb[i] = *(const uint4*)&Bt[(size_t)n * D_IN + k0 + q * 8];
        }
    };

    auto s_store = [&]() {
#pragma unroll
        for (int i = 0; i < 8; i++) {
            int li = tid + i * 256;
            int r  = li >> 4;
            int q  = li & 15;
            uint2 v;
            v.x = pack_f16x2(pa[i].x, pa[i].y);
            v.y = pack_f16x2(pa[i].z, pa[i].w);
            *(uint2*)&smA[SW128(r * 128 + q * 8)] = v;
        }
#pragma unroll
        for (int i = 0; i < 4; i++) {
            int li = tid + i * 256;
            int n  = li >> 3;
            int q  = li & 7;
            *(uint4*)&smB[SW128(n * 128 + q * 16)] = pb[i];
        }
    };

    auto compute = [&]() {
#pragma unroll
        for (int ks = 0; ks < 4; ks++) {
            const int kb = ks * 32;
            uint32_t af[2][4];
            uint32_t bf[8][2];
#pragma unroll
            for (int m = 0; m < 2; m++) {
                int row = warpM * 32 + m * 16 + aRowOff;
                ldsm4(af[m][0], af[m][1], af[m][2], af[m][3],
                      baseA + SW128(row * 128 + kb + aColOff));
            }
#pragma unroll
            for (int p = 0; p < 4; p++) {
                int row = warpN * 64 + p * 16 + bRowOff;
                ldsm4(bf[2 * p][0], bf[2 * p][1], bf[2 * p + 1][0], bf[2 * p + 1][1],
                      baseB + SW128(row * 128 + kb + bColOff));
            }
#pragma unroll
            for (int m = 0; m < 2; m++)
#pragma unroll
                for (int n = 0; n < 8; n++)
                    mma_f16(acc[m][n], af[m], bf[n]);
        }
    };

    g_load(0);
    s_store();
    __syncthreads();
#pragma unroll 1
    for (int kt = 0; kt < 8; kt++) {
        if (kt + 1 < 8) g_load((kt + 1) * 64);
        compute();
        __syncthreads();
        if (kt + 1 < 8) {
            s_store();
            __syncthreads();
        }
    }

#pragma unroll
    for (int m = 0; m < 2; m++) {
        int rHi = row0 + warpM * 32 + m * 16 + (lane >> 2);
        int rLo = rHi + 8;
#pragma unroll
        for (int n = 0; n < 8; n++) {
            int col = warpN * 64 + n * 8 + (lane & 3) * 2;
            float b0 = bias[col], b1 = bias[col + 1];
            if (rHi < M)
                *(uint32_t*)&C[(size_t)rHi * D_H + col] =
                    pack_f16x2(lrelu(acc[m][n][0] + b0), lrelu(acc[m][n][1] + b1));
            if (rLo < M)
                *(uint32_t*)&C[(size_t)rLo * D_H + col] =
                    pack_f16x2(lrelu(acc[m][n][2] + b0), lrelu(acc[m][n][3] + b1));
        }
    }
}

// =====================================================================
// generic fp16 HMMA GEMM, BN=64 (same as R15 passing version)
// =====================================================================
template<bool RELU, bool ADD_BIAS, bool SCALE_DINV>
__global__ __launch_bounds__(256) void gemm_f16_n64_kernel(
    const __half* __restrict__ A,
    const __half* __restrict__ Bt,
    const float* __restrict__ bias,
    __half* __restrict__ C,
    int M, int K)
{
    __shared__ __align__(1024) char smA[16384];
    __shared__ __align__(1024) char smB[8192];

    const int tid  = threadIdx.x;
    const int lane = tid & 31;
    const int warp = tid >> 5;
    const int warpM = warp & 3;
    const int warpN = warp >> 2;
    const int row0 = blockIdx.x * 128;

    const uint32_t baseA = smem_u32(smA);
    const uint32_t baseB = smem_u32(smB);

    float acc[2][4][4];
#pragma unroll
    for (int m = 0; m < 2; m++)
#pragma unroll
        for (int n = 0; n < 4; n++)
#pragma unroll
            for (int v = 0; v < 4; v++) acc[m][n][v] = 0.0f;

    const int matid = lane >> 3;
    const int matrow = lane & 7;
    const int aRowOff = (matid & 1) * 8 + matrow;
    const int aColOff = (matid >> 1) * 16;
    const int bRowOff = (matid >> 1) * 8 + matrow;
    const int bColOff = (matid & 1) * 16;

    uint4 pa[4], pb[2];

    auto g_load = [&](int k0) {
#pragma unroll
        for (int i = 0; i < 4; i++) {
            int li = tid + i * 256;
            int r  = li >> 3;
            int q  = li & 7;
            int gr = row0 + r;
            pa[i] = (gr < M) ? *(const uint4*)&A[(size_t)gr * K + k0 + q * 8]
                             : make_uint4(0u, 0u, 0u, 0u);
        }
#pragma unroll
        for (int i = 0; i < 2; i++) {
            int li = tid + i * 256;
            int n  = li >> 3;
            int q  = li & 7;
            pb[i] = *(const uint4*)&Bt[(size_t)n * K + k0 + q * 8];
        }
    };

    auto s_store = [&]() {
#pragma unroll
        for (int i = 0; i < 4; i++) {
            int li = tid + i * 256;
            int r  = li >> 3;
            int q  = li & 7;
            *(uint4*)&smA[SW128(r * 128 + q * 16)] = pa[i];
        }
#pragma unroll
        for (int i = 0; i < 2; i++) {
            int li = tid + i * 256;
            int n  = li >> 3;
            int q  = li & 7;
            *(uint4*)&smB[SW128(n * 128 + q * 16)] = pb[i];
        }
    };

    auto compute = [&]() {
#pragma unroll
        for (int ks = 0; ks < 4; ks++) {
            const int kb = ks * 32;
            uint32_t af[2][4];
            uint32_t bf[4][2];
#pragma unroll
            for (int m = 0; m < 2; m++) {
                int row = warpM * 32 + m * 16 + aRowOff;
                ldsm4(af[m][0], af[m][1], af[m][2], af[m][3],
                      baseA + SW128(row * 128 + kb + aColOff));
            }
#pragma unroll
            for (int p = 0; p < 2; p++) {
                int row = warpN * 32 + p * 16 + bRowOff;
                ldsm4(bf[2 * p][0], bf[2 * p][1], bf[2 * p + 1][0], bf[2 * p + 1][1],
                      baseB + SW128(row * 128 + kb + bColOff));
            }
#pragma unroll
            for (int m = 0; m < 2; m++)
#pragma unroll
                for (int n = 0; n < 4; n++)
                    mma_f16(acc[m][n], af[m], bf[n]);
        }
    };

    const int NT = K >> 6;
    g_load(0);
    s_store();
    __syncthreads();
#pragma unroll 1
    for (int kt = 0; kt < NT; kt++) {
        if (kt + 1 < NT) g_load((kt + 1) * 64);
        compute();
        __syncthreads();
        if (kt + 1 < NT) {
            s_store();
            __syncthreads();
        }
    }

#pragma unroll
    for (int m = 0; m < 2; m++) {
        int rHi = row0 + warpM * 32 + m * 16 + (lane >> 2);
        int rLo = rHi + 8;
        float scHi = 1.0f, scLo = 1.0f;
        if (SCALE_DINV) {
            if (rHi < M) scHi = g_dinv[rHi];
            if (rLo < M) scLo = g_dinv[rLo];
        }
#pragma unroll
        for (int n = 0; n < 4; n++) {
            int col = warpN * 32 + n * 8 + (lane & 3) * 2;
            float b0 = 0.f, b1 = 0.f;
            if (ADD_BIAS) { b0 = bias[col]; b1 = bias[col + 1]; }
            float v0 = acc[m][n][0], v1 = acc[m][n][1];
            float v2 = acc[m][n][2], v3 = acc[m][n][3];
            if (ADD_BIAS) { v0 += b0; v1 += b1; v2 += b0; v3 += b1; }
            if (SCALE_DINV) { v0 *= scHi; v1 *= scHi; v2 *= scLo; v3 *= scLo; }
            if (RELU) { v0 = lrelu(v0); v1 = lrelu(v1); v2 = lrelu(v2); v3 = lrelu(v3); }
            if (rHi < M) *(uint32_t*)&C[(size_t)rHi * D_O + col] = pack_f16x2(v0, v1);
            if (rLo < M) *(uint32_t*)&C[(size_t)rLo * D_O + col] = pack_f16x2(v2, v3);
        }
    }
}

// ---------------- weight transposes: all four weights -> fp16 K-major ----------------
__global__ void wprep_kernel(const float* __restrict__ W1,
                             const float* __restrict__ W2,
                             const float* __restrict__ Wg1,
                             const float* __restrict__ Wg2) {
    int idx = blockIdx.x * blockDim.x + threadIdx.x;
    if (idx < D_H * D_IN) {
        int n = idx >> 9, k = idx & 511;
        g_w1t[idx] = __float2half(W1[k * D_H + n]);
    } else if (idx < D_H * D_IN + D_O * D_H) {
        int j = idx - D_H * D_IN;
        int n = j >> 7, k = j & 127;
        g_w2t[j] = __float2half(W2[k * D_O + n]);
    } else if (idx < D_H * D_IN + D_O * D_H + D_O * D_O) {
        int j = idx - (D_H * D_IN + D_O * D_H);
        int n = j >> 6, k = j & 63;
        g_wg1t[j] = __float2half(Wg1[k * D_O + n]);
    } else if (idx < D_H * D_IN + D_O * D_H + 2 * D_O * D_O) {
        int j = idx - (D_H * D_IN + D_O * D_H + D_O * D_O);
        int n = j >> 6, k = j & 63;
        g_wg2t[j] = __float2half(Wg2[k * D_O + n]);
    }
}

// ---------------- degree count (int) + dinv ----------------
__global__ void count_deg_kernel(const int* __restrict__ dst) {
    int e = blockIdx.x * blockDim.x + threadIdx.x;
    if (e < E_EDGES) atomicAdd(&g_degi[dst[e]], 1);
}

__global__ void calc_dinv_kernel() {
    int i = blockIdx.x * blockDim.x + threadIdx.x;
    if (i < N_NODES) g_dinv[i] = rsqrtf(1.0f + (float)g_degi[i]);   // +1 self-loop
}

// ---------------- CSR build: exclusive scan of degrees + fill ----------------
__global__ void scan1_kernel() {
    __shared__ int sm[SCAN_BS];
    int i = blockIdx.x * SCAN_BS + threadIdx.x;
    int v = (i < N_NODES) ? g_degi[i] : 0;
    sm[threadIdx.x] = v;
    __syncthreads();
#pragma unroll
    for (int off = 1; off < SCAN_BS; off <<= 1) {
        int t = (threadIdx.x >= off) ? sm[threadIdx.x - off] : 0;
        __syncthreads();
        sm[threadIdx.x] += t;
        __syncthreads();
    }
    if (i < N_NODES) g_off[i] = sm[threadIdx.x] - v;       // block-local exclusive
    if (threadIdx.x == SCAN_BS - 1) g_bsum[blockIdx.x] = sm[threadIdx.x];
}

__global__ void scan2_kernel() {      // 1 block, 256 threads; SCAN_NB=196 <= 256
    __shared__ int sm[256];
    int v = (threadIdx.x < SCAN_NB) ? g_bsum[threadIdx.x] : 0;
    sm[threadIdx.x] = v;
    __syncthreads();
#pragma unroll
    for (int off = 1; off < 256; off <<= 1) {
        int t = (threadIdx.x >= off) ? sm[threadIdx.x - off] : 0;
        __syncthreads();
        sm[threadIdx.x] += t;
        __syncthreads();
    }
    if (threadIdx.x < SCAN_NB) g_bsum[threadIdx.x] = sm[threadIdx.x] - v;  // exclusive
    if (threadIdx.x == 255) g_off[N_NODES] = sm[255];       // total = E_EDGES
}

__global__ void scan3_kernel() {
    int i = blockIdx.x * blockDim.x + threadIdx.x;
    if (i < N_NODES) {
        int o = g_off[i] + g_bsum[i / SCAN_BS];
        g_off[i] = o;
        g_cursor[i] = o;
    }
}

__global__ void fill_kernel(const int* __restrict__ src, const int* __restrict__ dst) {
    int e = blockIdx.x * blockDim.x + threadIdx.x;
    if (e < E_EDGES) {
        int p = atomicAdd(&g_cursor[dst[e]], 1);
        g_elist[p] = src[e];
    }
}

// ---------------- gather: warp per node, LDG.128 (4 edges x 128B per warp-load) ----------------
// lane = eg*?  : eg = lane>>3 (edge subgroup 0..3), c8 = lane&7 (16B col chunk 0..7)
// out[d] = lrelu(dinv[d] * (sum_{e:dst=d} u[src[e]] + u[d]) + bias)
// LAST: write fp32 h4 AND fused classifier logits.
template<bool LAST>
__global__ __launch_bounds__(256) void gather_kernel(
    const __half* __restrict__ u,
    const float* __restrict__ bias,
    void* __restrict__ outv,
    const float* __restrict__ Wc,
    const float* __restrict__ bc,
    float* __restrict__ logits)
{
    int gw = (blockIdx.x * blockDim.x + threadIdx.x) >> 5;   // warp id = node
    const int lane = threadIdx.x & 31;
    if (gw >= N_NODES) return;                // grid is exact (100000 warps); never taken
    const int d = gw;
    const int beg = g_off[d];
    const int end = g_off[d + 1];
    const int eg = lane >> 3;                 // 0..3
    const int c8 = lane & 7;                  // 0..7
    const int colb = c8 * 8;                  // first col of this lane's 8-col chunk

    float acc[8];
#pragma unroll
    for (int k = 0; k < 8; k++) acc[k] = 0.0f;

    for (int base = beg; base < end; base += 32) {
        int li = base + lane;
        int idxv = (li < end) ? g_elist[li] : 0;
        int nblk = end - base;                // >0
#pragma unroll 2
        for (int j = 0; j * 4 < nblk && j < 8; j++) {
            int epos = j * 4 + eg;
            int s = __shfl_sync(0xffffffffu, idxv, epos);
            if (epos < nblk) {
                uint4 r = *(const uint4*)&u[(size_t)s * D_O + colb];
                float2 f;
                f = __half22float2(*(__half2*)&r.x); acc[0] += f.x; acc[1] += f.y;
                f = __half22float2(*(__half2*)&r.y); acc[2] += f.x; acc[3] += f.y;
                f = __half22float2(*(__half2*)&r.z); acc[4] += f.x; acc[5] += f.y;
                f = __half22float2(*(__half2*)&r.w); acc[6] += f.x; acc[7] += f.y;
            }
        }
    }
    // reduce across the 4 edge subgroups (lanes c8, c8+8, c8+16, c8+24)
#pragma unroll
    for (int k = 0; k < 8; k++) {
        acc[k] += __shfl_xor_sync(0xffffffffu, acc[k], 8);
        acc[k] += __shfl_xor_sync(0xffffffffu, acc[k], 16);
    }
    // self-loop term (each lane adds full value once, post-reduction)
    {
        uint4 r = *(const uint4*)&u[(size_t)d * D_O + colb];
        float2 f;
        f = __half22float2(*(__half2*)&r.x); acc[0] += f.x; acc[1] += f.y;
        f = __half22float2(*(__half2*)&r.y); acc[2] += f.x; acc[3] += f.y;
        f = __half22float2(*(__half2*)&r.z); acc[4] += f.x; acc[5] += f.y;
        f = __half22float2(*(__half2*)&r.w); acc[6] += f.x; acc[7] += f.y;
    }
    const float di = g_dinv[d];
    float v[8];
#pragma unroll
    for (int k = 0; k < 8; k++)
        v[k] = lrelu(di * acc[k] + bias[colb + k]);

    if (!LAST) {
        if (eg == 0) {
            __half* out = (__half*)outv;
            uint4 w;
            w.x = pack_f16x2(v[0], v[1]);
            w.y = pack_f16x2(v[2], v[3]);
            w.z = pack_f16x2(v[4], v[5]);
            w.w = pack_f16x2(v[6], v[7]);
            *(uint4*)&out[(size_t)d * D_O + colb] = w;
        }
    } else {
        float* out = (float*)outv;
        if (eg == 0) {
            float4 f0 = {v[0], v[1], v[2], v[3]};
            float4 f1 = {v[4], v[5], v[6], v[7]};
            *(float4*)&out[(size_t)d * D_O + colb]     = f0;
            *(float4*)&out[(size_t)d * D_O + colb + 4] = f1;
        }
        // fused classifier: logits[d] = h4[d] @ Wc + bc
        float p0 = 0.0f, p1 = 0.0f;
#pragma unroll
        for (int k = 0; k < 8; k++) {
            int col = colb + k;
            p0 += v[k] * Wc[col * 2 + 0];
            p1 += v[k] * Wc[col * 2 + 1];
        }
        // reduce over c8 (strides 1,2,4) — values replicated across eg, so this is exact
        p0 += __shfl_xor_sync(0xffffffffu, p0, 1);
        p1 += __shfl_xor_sync(0xffffffffu, p1, 1);
        p0 += __shfl_xor_sync(0xffffffffu, p0, 2);
        p1 += __shfl_xor_sync(0xffffffffu, p1, 2);
        p0 += __shfl_xor_sync(0xffffffffu, p0, 4);
        p1 += __shfl_xor_sync(0xffffffffu, p1, 4);
        if (lane == 0) {
            logits[(size_t)d * 2 + 0] = p0 + bc[0];
            logits[(size_t)d * 2 + 1] = p1 + bc[1];
        }
    }
}

// ---------------- host launcher ----------------
extern "C" void kernel_launch(void* const* d_in, const int* in_sizes, int n_in,
                              void* d_out, int out_size) {
    const float* x   = (const float*)d_in[0];
    const int*   ei  = (const int*)  d_in[1];
    const float* W1  = (const float*)d_in[2];
    const float* b1  = (const float*)d_in[3];
    const float* W2  = (const float*)d_in[4];
    const float* b2  = (const float*)d_in[5];
    const float* Wg1 = (const float*)d_in[6];
    const float* bg1 = (const float*)d_in[7];
    const float* Wg2 = (const float*)d_in[8];
    const float* bg2 = (const float*)d_in[9];
    const float* Wc  = (const float*)d_in[10];
    const float* bc  = (const float*)d_in[11];
    float* out = (float*)d_out;

    const int* src = ei;
    const int* dst = ei + E_EDGES;

    __half *h1, *h2, *h3, *u;
    int* degi;
    cudaGetSymbolAddress((void**)&h1,   g_h1);
    cudaGetSymbolAddress((void**)&h2,   g_h2);
    cudaGetSymbolAddress((void**)&h3,   g_h3);
    cudaGetSymbolAddress((void**)&u,    g_u);
    cudaGetSymbolAddress((void**)&degi, g_degi);

    __half *w2t, *wg1t, *wg2t;
    cudaGetSymbolAddress((void**)&w2t,  g_w2t);
    cudaGetSymbolAddress((void**)&wg1t, g_wg1t);
    cudaGetSymbolAddress((void**)&wg2t, g_wg2t);

    float* logits = out;                      // [N, 2]
    float* h4     = out + 2 * N_NODES;        // [N, 64]

    const int MBLK = (N_NODES + 127) / 128;   // 782

    // ---- CSR build (shared by both GCN layers) ----
    cudaMemsetAsync(degi, 0, N_NODES * sizeof(int));
    count_deg_kernel<<<(E_EDGES + 255) / 256, 256>>>(dst);
    calc_dinv_kernel<<<(N_NODES + 255) / 256, 256>>>();
    scan1_kernel<<<SCAN_NB, SCAN_BS>>>();
    scan2_kernel<<<1, 256>>>();
    scan3_kernel<<<(N_NODES + 255) / 256, 256>>>();
    fill_kernel<<<(E_EDGES + 255) / 256, 256>>>(src, dst);

    // ---- weights -> fp16 K-major ----
    const int WPREP = D_H * D_IN + D_O * D_H + 2 * D_O * D_O;   // 81920
    wprep_kernel<<<(WPREP + 255) / 256, 256>>>(W1, W2, Wg1, Wg2);

    // ---- encoder (fp16 HMMA) ----
    gemm1_f16_kernel<<<MBLK, 256>>>(x, b1, h1, N_NODES);
    gemm_f16_n64_kernel<true, true, false><<<MBLK, 256>>>(h1, w2t, b2, h2, N_NODES, D_H);

    const int GATHER_BLOCKS = (N_NODES * 32 + 255) / 256;   // 12500

    // ---- GCN layer 1: u = (h2 @ Wg1)*dinv ; gather -> h3 (f16) ----
    gemm_f16_n64_kernel<false, false, true><<<MBLK, 256>>>(h2, wg1t, nullptr, u, N_NODES, D_O);
    gather_kernel<false><<<GATHER_BLOCKS, 256>>>(u, bg1, h3, nullptr, nullptr, nullptr);

    // ---- GCN layer 2: u = (h3 @ Wg2)*dinv ; gather -> h4 (f32) + fused classifier ----
    gemm_f16_n64_kernel<false, false, true><<<MBLK, 256>>>(h3, wg2t, nullptr, u, N_NODES, D_O);
    gather_kernel<true><<<GATHER_BLOCKS, 256>>>(u, bg2, (void*)h4, Wc, bc, logits);
}

// round 17
// speedup vs baseline: 3.0407x; 1.0367x over previous
#include <cuda_runtime.h>
#include <cuda_fp16.h>
#include <cstdint>

#define N_NODES 100000
#define E_EDGES 3200000
#define D_IN   512
#define D_H    128
#define D_O    64
#define NEG_SLOPE 0.01f
#define SCAN_BS 512
#define SCAN_NB ((N_NODES + SCAN_BS - 1) / SCAN_BS)   // 196

// ---------------- scratch (device globals; no allocation allowed) ----------------
__device__ __half g_h1 [N_NODES * D_H];   // 25.6 MB (fp16)
__device__ __half g_h2 [N_NODES * D_O];   // 12.8 MB
__device__ __half g_h3 [N_NODES * D_O];   // 12.8 MB
__device__ __half g_u  [N_NODES * D_O];   // 12.8 MB (fp16 messages)
__device__ int    g_degi [N_NODES];
__device__ float  g_dinv [N_NODES];
__device__ int    g_off  [N_NODES + 1];   // CSR offsets (by dst)
__device__ int    g_cursor[N_NODES];
__device__ int    g_bsum [SCAN_NB];
__device__ int    g_elist[E_EDGES];       // 12.8 MB source list grouped by dst
__device__ __half g_w1t [D_H * D_IN];     // W1^T  [128][512] fp16 K-major
__device__ __half g_w2t [D_O * D_H];      // W2^T  [64][128]
__device__ __half g_wg1t[D_O * D_O];      // Wg1^T [64][64]
__device__ __half g_wg2t[D_O * D_O];      // Wg2^T [64][64]

__device__ __forceinline__ float lrelu(float v) {
    return v >= 0.0f ? v : NEG_SLOPE * v;
}

__device__ __forceinline__ uint32_t smem_u32(const void* p) {
    uint32_t a;
    asm("{ .reg .u64 t; cvta.to.shared.u64 t, %1; cvt.u32.u64 %0, t; }" : "=r"(a) : "l"(p));
    return a;
}
// pack two f32 -> f16x2 (lo in lower half, hi in upper half)
__device__ __forceinline__ uint32_t pack_f16x2(float lo, float hi) {
    uint32_t r;
    asm("cvt.rn.f16x2.f32 %0, %1, %2;" : "=r"(r) : "f"(hi), "f"(lo));
    return r;
}
__device__ __forceinline__ void ldsm4(uint32_t& r0, uint32_t& r1, uint32_t& r2, uint32_t& r3,
                                      uint32_t addr) {
    asm volatile("ldmatrix.sync.aligned.m8n8.x4.shared.b16 {%0,%1,%2,%3}, [%4];"
                 : "=r"(r0), "=r"(r1), "=r"(r2), "=r"(r3) : "r"(addr));
}
__device__ __forceinline__ void mma_f16(float* d, const uint32_t* a, const uint32_t* b) {
    asm volatile(
        "mma.sync.aligned.m16n8k16.row.col.f32.f16.f16.f32 "
        "{%0,%1,%2,%3}, {%4,%5,%6,%7}, {%8,%9}, {%0,%1,%2,%3};"
        : "+f"(d[0]), "+f"(d[1]), "+f"(d[2]), "+f"(d[3])
        : "r"(a[0]), "r"(a[1]), "r"(a[2]), "r"(a[3]), "r"(b[0]), "r"(b[1]));
}
// SW128 swizzle: XOR byte bits [6:4] with row bits [2:0] (128B rows)
#define SW128(o) ((o) ^ ((((uint32_t)(o)) >> 3) & 0x70))

// =====================================================================
// gemm1: fp16 HMMA GEMM  h1[M,128](f16) = lrelu(A[M,512](f32) @ W1 + b1)
// =====================================================================
__global__ __launch_bounds__(256) void gemm1_f16_kernel(
    const float* __restrict__ A,
    const float* __restrict__ bias,
    __half* __restrict__ C,
    int M)
{
    __shared__ __align__(1024) char smA[16384];   // 128 x 64 f16, SW128
    __shared__ __align__(1024) char smB[16384];   // 128(n) x 64(k) f16, SW128

    const int tid  = threadIdx.x;
    const int lane = tid & 31;
    const int warp = tid >> 5;
    const int warpM = warp & 3;
    const int warpN = warp >> 2;
    const int row0 = blockIdx.x * 128;

    const uint32_t baseA = smem_u32(smA);
    const uint32_t baseB = smem_u32(smB);
    const __half* __restrict__ Bt = g_w1t;

    float acc[2][8][4];
#pragma unroll
    for (int m = 0; m < 2; m++)
#pragma unroll
        for (int n = 0; n < 8; n++)
#pragma unroll
            for (int v = 0; v < 4; v++) acc[m][n][v] = 0.0f;

    const int matid = lane >> 3;
    const int matrow = lane & 7;
    const int aRowOff = (matid & 1) * 8 + matrow;
    const int aColOff = (matid >> 1) * 16;
    const int bRowOff = (matid >> 1) * 8 + matrow;
    const int bColOff = (matid & 1) * 16;

    float4 pa[8];
    uint4  pb[4];

    auto g_load = [&](int k0) {
#pragma unroll
        for (int i = 0; i < 8; i++) {
            int li = tid + i * 256;
            int r  = li >> 4;
            int q  = li & 15;
            int gr = row0 + r;
            pa[i] = (gr < M) ? *(const float4*)&A[(size_t)gr * D_IN + k0 + q * 4]
                             : make_float4(0.f, 0.f, 0.f, 0.f);
        }
#pragma unroll
        for (int i = 0; i < 4; i++) {
            int li = tid + i * 256;
            int n  = li >> 3;
            int q  = li & 7;
            pb[i] = *(const uint4*)&Bt[(size_t)n * D_IN + k0 + q * 8];
        }
    };

    auto s_store = [&]() {
#pragma unroll
        for (int i = 0; i < 8; i++) {
            int li = tid + i * 256;
            int r  = li >> 4;
            int q  = li & 15;
            uint2 v;
            v.x = pack_f16x2(pa[i].x, pa[i].y);
            v.y = pack_f16x2(pa[i].z, pa[i].w);
            *(uint2*)&smA[SW128(r * 128 + q * 8)] = v;
        }
#pragma unroll
        for (int i = 0; i < 4; i++) {
            int li = tid + i * 256;
            int n  = li >> 3;
            int q  = li & 7;
            *(uint4*)&smB[SW128(n * 128 + q * 16)] = pb[i];
        }
    };

    auto compute = [&]() {
#pragma unroll
        for (int ks = 0; ks < 4; ks++) {
            const int kb = ks * 32;
            uint32_t af[2][4];
            uint32_t bf[8][2];
#pragma unroll
            for (int m = 0; m < 2; m++) {
                int row = warpM * 32 + m * 16 + aRowOff;
                ldsm4(af[m][0], af[m][1], af[m][2], af[m][3],
                      baseA + SW128(row * 128 + kb + aColOff));
            }
#pragma unroll
            for (int p = 0; p < 4; p++) {
                int row = warpN * 64 + p * 16 + bRowOff;
                ldsm4(bf[2 * p][0], bf[2 * p][1], bf[2 * p + 1][0], bf[2 * p + 1][1],
                      baseB + SW128(row * 128 + kb + bColOff));
            }
#pragma unroll
            for (int m = 0; m < 2; m++)
#pragma unroll
                for (int n = 0; n < 8; n++)
                    mma_f16(acc[m][n], af[m], bf[n]);
        }
    };

    g_load(0);
    s_store();
    __syncthreads();
#pragma unroll 1
    for (int kt = 0; kt < 8; kt++) {
        if (kt + 1 < 8) g_load((kt + 1) * 64);
        compute();
        __syncthreads();
        if (kt + 1 < 8) {
            s_store();
            __syncthreads();
        }
    }

#pragma unroll
    for (int m = 0; m < 2; m++) {
        int rHi = row0 + warpM * 32 + m * 16 + (lane >> 2);
        int rLo = rHi + 8;
#pragma unroll
        for (int n = 0; n < 8; n++) {
            int col = warpN * 64 + n * 8 + (lane & 3) * 2;
            float b0 = bias[col], b1 = bias[col + 1];
            if (rHi < M)
                *(uint32_t*)&C[(size_t)rHi * D_H + col] =
                    pack_f16x2(lrelu(acc[m][n][0] + b0), lrelu(acc[m][n][1] + b1));
            if (rLo < M)
                *(uint32_t*)&C[(size_t)rLo * D_H + col] =
                    pack_f16x2(lrelu(acc[m][n][2] + b0), lrelu(acc[m][n][3] + b1));
        }
    }
}

// =====================================================================
// generic fp16 HMMA GEMM, BN=64 (same as R16 passing version)
// =====================================================================
template<bool RELU, bool ADD_BIAS, bool SCALE_DINV>
__global__ __launch_bounds__(256) void gemm_f16_n64_kernel(
    const __half* __restrict__ A,
    const __half* __restrict__ Bt,
    const float* __restrict__ bias,
    __half* __restrict__ C,
    int M, int K)
{
    __shared__ __align__(1024) char smA[16384];
    __shared__ __align__(1024) char smB[8192];

    const int tid  = threadIdx.x;
    const int lane = tid & 31;
    const int warp = tid >> 5;
    const int warpM = warp & 3;
    const int warpN = warp >> 2;
    const int row0 = blockIdx.x * 128;

    const uint32_t baseA = smem_u32(smA);
    const uint32_t baseB = smem_u32(smB);

    float acc[2][4][4];
#pragma unroll
    for (int m = 0; m < 2; m++)
#pragma unroll
        for (int n = 0; n < 4; n++)
#pragma unroll
            for (int v = 0; v < 4; v++) acc[m][n][v] = 0.0f;

    const int matid = lane >> 3;
    const int matrow = lane & 7;
    const int aRowOff = (matid & 1) * 8 + matrow;
    const int aColOff = (matid >> 1) * 16;
    const int bRowOff = (matid >> 1) * 8 + matrow;
    const int bColOff = (matid & 1) * 16;

    uint4 pa[4], pb[2];

    auto g_load = [&](int k0) {
#pragma unroll
        for (int i = 0; i < 4; i++) {
            int li = tid + i * 256;
            int r  = li >> 3;
            int q  = li & 7;
            int gr = row0 + r;
            pa[i] = (gr < M) ? *(const uint4*)&A[(size_t)gr * K + k0 + q * 8]
                             : make_uint4(0u, 0u, 0u, 0u);
        }
#pragma unroll
        for (int i = 0; i < 2; i++) {
            int li = tid + i * 256;
            int n  = li >> 3;
            int q  = li & 7;
            pb[i] = *(const uint4*)&Bt[(size_t)n * K + k0 + q * 8];
        }
    };

    auto s_store = [&]() {
#pragma unroll
        for (int i = 0; i < 4; i++) {
            int li = tid + i * 256;
            int r  = li >> 3;
            int q  = li & 7;
            *(uint4*)&smA[SW128(r * 128 + q * 16)] = pa[i];
        }
#pragma unroll
        for (int i = 0; i < 2; i++) {
            int li = tid + i * 256;
            int n  = li >> 3;
            int q  = li & 7;
            *(uint4*)&smB[SW128(n * 128 + q * 16)] = pb[i];
        }
    };

    auto compute = [&]() {
#pragma unroll
        for (int ks = 0; ks < 4; ks++) {
            const int kb = ks * 32;
            uint32_t af[2][4];
            uint32_t bf[4][2];
#pragma unroll
            for (int m = 0; m < 2; m++) {
                int row = warpM * 32 + m * 16 + aRowOff;
                ldsm4(af[m][0], af[m][1], af[m][2], af[m][3],
                      baseA + SW128(row * 128 + kb + aColOff));
            }
#pragma unroll
            for (int p = 0; p < 2; p++) {
                int row = warpN * 32 + p * 16 + bRowOff;
                ldsm4(bf[2 * p][0], bf[2 * p][1], bf[2 * p + 1][0], bf[2 * p + 1][1],
                      baseB + SW128(row * 128 + kb + bColOff));
            }
#pragma unroll
            for (int m = 0; m < 2; m++)
#pragma unroll
                for (int n = 0; n < 4; n++)
                    mma_f16(acc[m][n], af[m], bf[n]);
        }
    };

    const int NT = K >> 6;
    g_load(0);
    s_store();
    __syncthreads();
#pragma unroll 1
    for (int kt = 0; kt < NT; kt++) {
        if (kt + 1 < NT) g_load((kt + 1) * 64);
        compute();
        __syncthreads();
        if (kt + 1 < NT) {
            s_store();
            __syncthreads();
        }
    }

#pragma unroll
    for (int m = 0; m < 2; m++) {
        int rHi = row0 + warpM * 32 + m * 16 + (lane >> 2);
        int rLo = rHi + 8;
        float scHi = 1.0f, scLo = 1.0f;
        if (SCALE_DINV) {
            if (rHi < M) scHi = g_dinv[rHi];
            if (rLo < M) scLo = g_dinv[rLo];
        }
#pragma unroll
        for (int n = 0; n < 4; n++) {
            int col = warpN * 32 + n * 8 + (lane & 3) * 2;
            float b0 = 0.f, b1 = 0.f;
            if (ADD_BIAS) { b0 = bias[col]; b1 = bias[col + 1]; }
            float v0 = acc[m][n][0], v1 = acc[m][n][1];
            float v2 = acc[m][n][2], v3 = acc[m][n][3];
            if (ADD_BIAS) { v0 += b0; v1 += b1; v2 += b0; v3 += b1; }
            if (SCALE_DINV) { v0 *= scHi; v1 *= scHi; v2 *= scLo; v3 *= scLo; }
            if (RELU) { v0 = lrelu(v0); v1 = lrelu(v1); v2 = lrelu(v2); v3 = lrelu(v3); }
            if (rHi < M) *(uint32_t*)&C[(size_t)rHi * D_O + col] = pack_f16x2(v0, v1);
            if (rLo < M) *(uint32_t*)&C[(size_t)rLo * D_O + col] = pack_f16x2(v2, v3);
        }
    }
}

// ---------------- weight transposes: all four weights -> fp16 K-major ----------------
__global__ void wprep_kernel(const float* __restrict__ W1,
                             const float* __restrict__ W2,
                             const float* __restrict__ Wg1,
                             const float* __restrict__ Wg2) {
    int idx = blockIdx.x * blockDim.x + threadIdx.x;
    if (idx < D_H * D_IN) {
        int n = idx >> 9, k = idx & 511;
        g_w1t[idx] = __float2half(W1[k * D_H + n]);
    } else if (idx < D_H * D_IN + D_O * D_H) {
        int j = idx - D_H * D_IN;
        int n = j >> 7, k = j & 127;
        g_w2t[j] = __float2half(W2[k * D_O + n]);
    } else if (idx < D_H * D_IN + D_O * D_H + D_O * D_O) {
        int j = idx - (D_H * D_IN + D_O * D_H);
        int n = j >> 6, k = j & 63;
        g_wg1t[j] = __float2half(Wg1[k * D_O + n]);
    } else if (idx < D_H * D_IN + D_O * D_H + 2 * D_O * D_O) {
        int j = idx - (D_H * D_IN + D_O * D_H + D_O * D_O);
        int n = j >> 6, k = j & 63;
        g_wg2t[j] = __float2half(Wg2[k * D_O + n]);
    }
}

// ---------------- degree count (int) + dinv ----------------
__global__ void count_deg_kernel(const int* __restrict__ dst) {
    int e = blockIdx.x * blockDim.x + threadIdx.x;
    if (e < E_EDGES) atomicAdd(&g_degi[dst[e]], 1);
}

__global__ void calc_dinv_kernel() {
    int i = blockIdx.x * blockDim.x + threadIdx.x;
    if (i < N_NODES) g_dinv[i] = rsqrtf(1.0f + (float)g_degi[i]);   // +1 self-loop
}

// ---------------- CSR build: exclusive scan of degrees + fill ----------------
__global__ void scan1_kernel() {
    __shared__ int sm[SCAN_BS];
    int i = blockIdx.x * SCAN_BS + threadIdx.x;
    int v = (i < N_NODES) ? g_degi[i] : 0;
    sm[threadIdx.x] = v;
    __syncthreads();
#pragma unroll
    for (int off = 1; off < SCAN_BS; off <<= 1) {
        int t = (threadIdx.x >= off) ? sm[threadIdx.x - off] : 0;
        __syncthreads();
        sm[threadIdx.x] += t;
        __syncthreads();
    }
    if (i < N_NODES) g_off[i] = sm[threadIdx.x] - v;       // block-local exclusive
    if (threadIdx.x == SCAN_BS - 1) g_bsum[blockIdx.x] = sm[threadIdx.x];
}

__global__ void scan2_kernel() {      // 1 block, 256 threads; SCAN_NB=196 <= 256
    __shared__ int sm[256];
    int v = (threadIdx.x < SCAN_NB) ? g_bsum[threadIdx.x] : 0;
    sm[threadIdx.x] = v;
    __syncthreads();
#pragma unroll
    for (int off = 1; off < 256; off <<= 1) {
        int t = (threadIdx.x >= off) ? sm[threadIdx.x - off] : 0;
        __syncthreads();
        sm[threadIdx.x] += t;
        __syncthreads();
    }
    if (threadIdx.x < SCAN_NB) g_bsum[threadIdx.x] = sm[threadIdx.x] - v;  // exclusive
    if (threadIdx.x == 255) g_off[N_NODES] = sm[255];       // total = E_EDGES
}

__global__ void scan3_kernel() {
    int i = blockIdx.x * blockDim.x + threadIdx.x;
    if (i < N_NODES) {
        int o = g_off[i] + g_bsum[i / SCAN_BS];
        g_off[i] = o;
        g_cursor[i] = o;
    }
}

__global__ void fill_kernel(const int* __restrict__ src, const int* __restrict__ dst) {
    int e = blockIdx.x * blockDim.x + threadIdx.x;
    if (e < E_EDGES) {
        int p = atomicAdd(&g_cursor[dst[e]], 1);
        g_elist[p] = src[e];
    }
}

// ---------------- gather: warp per node, LDG.128 (4 edges x 128B per warp-load) ----------------
// out[d] = lrelu(dinv[d] * (sum_{e:dst=d} u[src[e]] + u[d]) + bias)
// LAST: write fp32 h4 AND fused classifier logits.
template<bool LAST>
__global__ __launch_bounds__(256) void gather_kernel(
    const __half* __restrict__ u,
    const float* __restrict__ bias,
    void* __restrict__ outv,
    const float* __restrict__ Wc,
    const float* __restrict__ bc,
    float* __restrict__ logits)
{
    int gw = (blockIdx.x * blockDim.x + threadIdx.x) >> 5;   // warp id = node
    const int lane = threadIdx.x & 31;
    if (gw >= N_NODES) return;
    const int d = gw;
    const int beg = g_off[d];
    const int end = g_off[d + 1];
    const int eg = lane >> 3;                 // 0..3
    const int c8 = lane & 7;                  // 0..7
    const int colb = c8 * 8;                  // first col of this lane's 8-col chunk

    float acc[8];
#pragma unroll
    for (int k = 0; k < 8; k++) acc[k] = 0.0f;

    for (int base = beg; base < end; base += 32) {
        int li = base + lane;
        int idxv = (li < end) ? g_elist[li] : 0;
        int nblk = end - base;                // >0
#pragma unroll 2
        for (int j = 0; j * 4 < nblk && j < 8; j++) {
            int epos = j * 4 + eg;
            int s = __shfl_sync(0xffffffffu, idxv, epos);
            if (epos < nblk) {
                uint4 r = *(const uint4*)&u[(size_t)s * D_O + colb];
                float2 f;
                f = __half22float2(*(__half2*)&r.x); acc[0] += f.x; acc[1] += f.y;
                f = __half22float2(*(__half2*)&r.y); acc[2] += f.x; acc[3] += f.y;
                f = __half22float2(*(__half2*)&r.z); acc[4] += f.x; acc[5] += f.y;
                f = __half22float2(*(__half2*)&r.w); acc[6] += f.x; acc[7] += f.y;
            }
        }
    }
    // reduce across the 4 edge subgroups (lanes c8, c8+8, c8+16, c8+24)
#pragma unroll
    for (int k = 0; k < 8; k++) {
        acc[k] += __shfl_xor_sync(0xffffffffu, acc[k], 8);
        acc[k] += __shfl_xor_sync(0xffffffffu, acc[k], 16);
    }
    // self-loop term (each lane adds full value once, post-reduction)
    {
        uint4 r = *(const uint4*)&u[(size_t)d * D_O + colb];
        float2 f;
        f = __half22float2(*(__half2*)&r.x); acc[0] += f.x; acc[1] += f.y;
        f = __half22float2(*(__half2*)&r.y); acc[2] += f.x; acc[3] += f.y;
        f = __half22float2(*(__half2*)&r.z); acc[4] += f.x; acc[5] += f.y;
        f = __half22float2(*(__half2*)&r.w); acc[6] += f.x; acc[7] += f.y;
    }
    const float di = g_dinv[d];
    float v[8];
#pragma unroll
    for (int k = 0; k < 8; k++)
        v[k] = lrelu(di * acc[k] + bias[colb + k]);

    if (!LAST) {
        if (eg == 0) {
            __half* out = (__half*)outv;
            uint4 w;
            w.x = pack_f16x2(v[0], v[1]);
            w.y = pack_f16x2(v[2], v[3]);
            w.z = pack_f16x2(v[4], v[5]);
            w.w = pack_f16x2(v[6], v[7]);
            *(uint4*)&out[(size_t)d * D_O + colb] = w;
        }
    } else {
        float* out = (float*)outv;
        if (eg == 0) {
            float4 f0 = {v[0], v[1], v[2], v[3]};
            float4 f1 = {v[4], v[5], v[6], v[7]};
            *(float4*)&out[(size_t)d * D_O + colb]     = f0;
            *(float4*)&out[(size_t)d * D_O + colb + 4] = f1;
        }
        // fused classifier: logits[d] = h4[d] @ Wc + bc
        float p0 = 0.0f, p1 = 0.0f;
#pragma unroll
        for (int k = 0; k < 8; k++) {
            int col = colb + k;
            p0 += v[k] * Wc[col * 2 + 0];
            p1 += v[k] * Wc[col * 2 + 1];
        }
        p0 += __shfl_xor_sync(0xffffffffu, p0, 1);
        p1 += __shfl_xor_sync(0xffffffffu, p1, 1);
        p0 += __shfl_xor_sync(0xffffffffu, p0, 2);
        p1 += __shfl_xor_sync(0xffffffffu, p1, 2);
        p0 += __shfl_xor_sync(0xffffffffu, p0, 4);
        p1 += __shfl_xor_sync(0xffffffffu, p1, 4);
        if (lane == 0) {
            logits[(size_t)d * 2 + 0] = p0 + bc[0];
            logits[(size_t)d * 2 + 1] = p1 + bc[1];
        }
    }
}

// ---------------- host launcher (fork-join two-stream schedule) ----------------
extern "C" void kernel_launch(void* const* d_in, const int* in_sizes, int n_in,
                              void* d_out, int out_size) {
    const float* x   = (const float*)d_in[0];
    const int*   ei  = (const int*)  d_in[1];
    const float* W1  = (const float*)d_in[2];
    const float* b1  = (const float*)d_in[3];
    const float* W2  = (const float*)d_in[4];
    const float* b2  = (const float*)d_in[5];
    const float* Wg1 = (const float*)d_in[6];
    const float* bg1 = (const float*)d_in[7];
    const float* Wg2 = (const float*)d_in[8];
    const float* bg2 = (const float*)d_in[9];
    const float* Wc  = (const float*)d_in[10];
    const float* bc  = (const float*)d_in[11];
    float* out = (float*)d_out;

    const int* src = ei;
    const int* dst = ei + E_EDGES;

    __half *h1, *h2, *h3, *u;
    int* degi;
    cudaGetSymbolAddress((void**)&h1,   g_h1);
    cudaGetSymbolAddress((void**)&h2,   g_h2);
    cudaGetSymbolAddress((void**)&h3,   g_h3);
    cudaGetSymbolAddress((void**)&u,    g_u);
    cudaGetSymbolAddress((void**)&degi, g_degi);

    __half *w2t, *wg1t, *wg2t;
    cudaGetSymbolAddress((void**)&w2t,  g_w2t);
    cudaGetSymbolAddress((void**)&wg1t, g_wg1t);
    cudaGetSymbolAddress((void**)&wg2t, g_wg2t);

    float* logits = out;                      // [N, 2]
    float* h4     = out + 2 * N_NODES;        // [N, 64]

    const int MBLK = (N_NODES + 127) / 128;   // 782

    // lazily-created side stream + events (no device-memory allocation;
    // per-call work identical every call — only created on the very first call)
    static cudaStream_t s2 = nullptr;
    static cudaEvent_t evFork = nullptr, evDinv = nullptr, evFill = nullptr;
    if (s2 == nullptr) {
        cudaStreamCreateWithFlags(&s2, cudaStreamNonBlocking);
        cudaEventCreateWithFlags(&evFork, cudaEventDisableTiming);
        cudaEventCreateWithFlags(&evDinv, cudaEventDisableTiming);
        cudaEventCreateWithFlags(&evFill, cudaEventDisableTiming);
    }

    // ---- fork: CSR build chain on s2, encoder on main (stream 0) ----
    cudaEventRecord(evFork, 0);
    cudaStreamWaitEvent(s2, evFork, 0);

    cudaMemsetAsync(degi, 0, N_NODES * sizeof(int), s2);
    count_deg_kernel<<<(E_EDGES + 255) / 256, 256, 0, s2>>>(dst);       // launch 1
    calc_dinv_kernel<<<(N_NODES + 255) / 256, 256, 0, s2>>>();          // launch 2
    cudaEventRecord(evDinv, s2);

    const int WPREP = D_H * D_IN + D_O * D_H + 2 * D_O * D_O;           // 81920
    wprep_kernel<<<(WPREP + 255) / 256, 256>>>(W1, W2, Wg1, Wg2);       // launch 3
    gemm1_f16_kernel<<<MBLK, 256>>>(x, b1, h1, N_NODES);                // launch 4 (profiled)

    scan1_kernel<<<SCAN_NB, SCAN_BS, 0, s2>>>();                        // launch 5
    scan2_kernel<<<1, 256, 0, s2>>>();
    scan3_kernel<<<(N_NODES + 255) / 256, 256, 0, s2>>>();
    fill_kernel<<<(E_EDGES + 255) / 256, 256, 0, s2>>>(src, dst);
    cudaEventRecord(evFill, s2);

    gemm_f16_n64_kernel<true, true, false><<<MBLK, 256>>>(h1, w2t, b2, h2, N_NODES, D_H);

    // ---- join 1: GCN gemm needs dinv ----
    cudaStreamWaitEvent(0, evDinv, 0);
    gemm_f16_n64_kernel<false, false, true><<<MBLK, 256>>>(h2, wg1t, nullptr, u, N_NODES, D_O);

    const int GATHER_BLOCKS = (N_NODES * 32 + 255) / 256;   // 12500

    // ---- join 2: gather needs CSR fill ----
    cudaStreamWaitEvent(0, evFill, 0);
    gather_kernel<false><<<GATHER_BLOCKS, 256>>>(u, bg1, h3, nullptr, nullptr, nullptr);

    // ---- GCN layer 2 + fused classifier ----
    gemm_f16_n64_kernel<false, false, true><<<MBLK, 256>>>(h3, wg2t, nullptr, u, N_NODES, D_O);
    gather_kernel<true><<<GATHER_BLOCKS, 256>>>(u, bg2, (void*)h4, Wc, bc, logits);
}